// round 12
// baseline (speedup 1.0000x reference)
#include <cuda_runtime.h>
#include <cuda_bf16.h>
#include <cuda_fp16.h>
#include <math.h>
#include <stdint.h>

#define BT 131072
typedef unsigned long long u64;
typedef unsigned int u32;
typedef __nv_bfloat16 bf16;

// fp32 scratch
__device__ float g_xz1 [134217728];   // [BT,1024]
__device__ float g_xz2 [67108864];    // [BT, 512]
__device__ float g_xzd1[262144];      // [B, 512]
__device__ float g_bp  [4096];        // permuted biases
// bf16 hi/lo planes
__device__ bf16 g_xhi  [8388608],  g_xlo  [8388608];
__device__ bf16 g_h1hi [33554432], g_h1lo [33554432];
__device__ bf16 g_hd1hi[16777216], g_hd1lo[16777216];
__device__ bf16 g_zhi  [65536],    g_zlo  [65536];
__device__ bf16 g_whi  [409600],   g_wlo  [409600];

__device__ __forceinline__ float sigm(float x) {
    return __fdividef(1.0f, 1.0f + __expf(-x));
}
__device__ __forceinline__ u32 smem_u32(const void* p) {
    u32 a; asm("{ .reg .u64 t; cvta.to.shared.u64 t, %1; cvt.u32.u64 %0, t; }"
               : "=r"(a) : "l"(p));
    return a;
}
__device__ __forceinline__ u32 pkbf(float a, float b) {
    __nv_bfloat162 t = __floats2bfloat162_rn(a, b);
    return *reinterpret_cast<u32*>(&t);
}
__device__ __forceinline__ float bres(float x) {
    return x - __bfloat162float(__float2bfloat16_rn(x));
}
__device__ __forceinline__ u32 pkh2(float a, float b) {
    __half2 h = __floats2half2_rn(a, b);
    return *reinterpret_cast<u32*>(&h);
}
__device__ __forceinline__ u64 pkh64(float a, float b, float c, float d) {
    return (u64)pkh2(a, b) | ((u64)pkh2(c, d) << 32);
}
__device__ __forceinline__ float hres(float x) {
    return x - __half2float(__float2half_rn(x));
}
__device__ __forceinline__ void ldsm4(u32 &r0, u32 &r1, u32 &r2, u32 &r3, u32 a) {
    asm volatile("ldmatrix.sync.aligned.m8n8.x4.shared.b16 {%0,%1,%2,%3}, [%4];"
                 : "=r"(r0), "=r"(r1), "=r"(r2), "=r"(r3) : "r"(a));
}
__device__ __forceinline__ void ldsm4t(u32 &r0, u32 &r1, u32 &r2, u32 &r3, u32 a) {
    asm volatile("ldmatrix.sync.aligned.m8n8.x4.trans.shared.b16 {%0,%1,%2,%3}, [%4];"
                 : "=r"(r0), "=r"(r1), "=r"(r2), "=r"(r3) : "r"(a));
}
__device__ __forceinline__ void mma_bf16(float* c, const u32* a, const u32* b) {
    asm volatile("mma.sync.aligned.m16n8k16.row.col.f32.bf16.bf16.f32 "
                 "{%0,%1,%2,%3}, {%4,%5,%6,%7}, {%8,%9}, {%0,%1,%2,%3};"
                 : "+f"(c[0]), "+f"(c[1]), "+f"(c[2]), "+f"(c[3])
                 : "r"(a[0]), "r"(a[1]), "r"(a[2]), "r"(a[3]), "r"(b[0]), "r"(b[1]));
}
__device__ __forceinline__ void mma_f16(float* c, const u32* a, u32 b0, u32 b1) {
    asm volatile("mma.sync.aligned.m16n8k16.row.col.f32.f16.f16.f32 "
                 "{%0,%1,%2,%3}, {%4,%5,%6,%7}, {%8,%9}, {%0,%1,%2,%3};"
                 : "+f"(c[0]), "+f"(c[1]), "+f"(c[2]), "+f"(c[3])
                 : "r"(a[0]), "r"(a[1]), "r"(a[2]), "r"(a[3]), "r"(b0), "r"(b1));
}
__device__ __forceinline__ void cp8(u32 d, const void* s) {
    asm volatile("cp.async.ca.shared.global [%0], [%1], 8;" :: "r"(d), "l"(s));
}
__device__ __forceinline__ void cp16(u32 d, const void* s) {
    asm volatile("cp.async.ca.shared.global [%0], [%1], 16;" :: "r"(d), "l"(s));
}

// ---------------------------------------------------------------------------
// Converters
// ---------------------------------------------------------------------------
__global__ void cvt_x(const float* __restrict__ s, bf16* __restrict__ hi,
                      bf16* __restrict__ lo, int n4)
{
    for (int i = blockIdx.x * blockDim.x + threadIdx.x; i < n4;
         i += gridDim.x * blockDim.x) {
        float4 v = ((const float4*)s)[i];
        ((uint2*)hi)[i] = make_uint2(pkbf(v.x, v.y), pkbf(v.z, v.w));
        ((uint2*)lo)[i] = make_uint2(pkbf(bres(v.x), bres(v.y)),
                                     pkbf(bres(v.z), bres(v.w)));
    }
}

// Gate-interleave permuted W planes: out col n -> orig col (n&3)*HU + (n>>2)
__global__ void cvt_wperm(const float* w0, const float* w1, const float* w2,
                          const float* w3, const float* w4, const float* w5,
                          const float* w6, const float* w7,
                          bf16* __restrict__ hi, bf16* __restrict__ lo)
{
    const float* W; int K, HU, off;
    switch (blockIdx.y) {
        case 0: W = w0; K = 64;  HU = 128; off = 0;      break;
        case 1: W = w1; K = 64;  HU = 128; off = 32768;  break;
        case 2: W = w2; K = 256; HU = 64;  off = 65536;  break;
        case 3: W = w3; K = 256; HU = 64;  off = 131072; break;
        case 4: W = w4; K = 128; HU = 64;  off = 196608; break;
        case 5: W = w5; K = 128; HU = 64;  off = 229376; break;
        case 6: W = w6; K = 128; HU = 128; off = 262144; break;
        default: W = w7; K = 128; HU = 128; off = 327680; break;
    }
    const int NG = 4 * HU, tot = K * NG;
    for (int i = blockIdx.x * blockDim.x + threadIdx.x; i < tot;
         i += gridDim.x * blockDim.x) {
        int n = i % NG, k = i / NG;
        int oc = (n & 3) * HU + (n >> 2);
        float v = W[(size_t)k * NG + oc];
        hi[off + i] = __float2bfloat16_rn(v);
        lo[off + i] = __float2bfloat16_rn(bres(v));
    }
}

__global__ void cvt_bperm(const float* b0, const float* b1, const float* b2,
                          const float* b3, const float* b4, const float* b5,
                          const float* b6, const float* b7,
                          float* __restrict__ bp)
{
    const float* b; int HU, off;
    switch (blockIdx.y) {
        case 0: b = b0; HU = 128; off = 0;    break;
        case 1: b = b1; HU = 128; off = 512;  break;
        case 2: b = b2; HU = 64;  off = 1024; break;
        case 3: b = b3; HU = 64;  off = 1280; break;
        case 4: b = b4; HU = 64;  off = 1536; break;
        case 5: b = b5; HU = 64;  off = 1792; break;
        case 6: b = b6; HU = 128; off = 2048; break;
        default: b = b7; HU = 128; off = 2560; break;
    }
    int n = threadIdx.x;
    if (n < 4 * HU) bp[off + n] = b[(n & 3) * HU + (n >> 2)];
}

// ---------------------------------------------------------------------------
// hgemm2 (R11, proven): C = A@W + bias, pre-split bf16 planes, cp.async.
// ---------------------------------------------------------------------------
template<int NT>
__device__ __forceinline__ void g2s_chunk(
    u32 sbase, const bf16* Ahi, const bf16* Alo,
    const bf16* Whi, const bf16* Wlo,
    int bm, int bn, int k0, int K, int Nw, int tid)
{
    constexpr int PA = 80, ASZ = 128 * PA;
    constexpr int PB = NT * 2 + 16, WSZ = 32 * PB;
    constexpr int WOPS = NT / 32;
    {
        int row = tid & 127;
        const bf16* src = ((tid & 128) ? Alo : Ahi) + (size_t)(bm + row) * K + k0;
        u32 dst = sbase + ((tid & 128) ? ASZ : 0) + row * PA;
        #pragma unroll
        for (int i = 0; i < 8; i++)
            cp8(dst + i * 8, (const char*)src + i * 8);
    }
    {
        int idx = tid & 127, row = idx >> 2, seg = idx & 3;
        const bf16* src = ((tid & 128) ? Wlo : Whi)
                          + (size_t)(k0 + row) * Nw + bn + seg * (NT / 4);
        u32 dst = sbase + 2 * ASZ + ((tid & 128) ? WSZ : 0) + row * PB + seg * (NT / 2);
        #pragma unroll
        for (int i = 0; i < WOPS; i++)
            cp16(dst + i * 16, (const char*)src + i * 16);
    }
}

template<int NT, int WM, int WN>
__global__ __launch_bounds__(256, 2)
void hgemm2(const bf16* __restrict__ Ahi, const bf16* __restrict__ Alo,
            const bf16* __restrict__ Whi0, const bf16* __restrict__ Wlo0,
            const bf16* __restrict__ Whi1, const bf16* __restrict__ Wlo1,
            const float* __restrict__ bias0, const float* __restrict__ bias1,
            float* __restrict__ C, int K, int Nw, int ldc, int coff)
{
    constexpr int PA = 80, ASZ = 128 * PA;
    constexpr int PB = NT * 2 + 16, WSZ = 32 * PB;
    constexpr int STG = 2 * ASZ + 2 * WSZ;
    constexpr int MW = 128 / WM, NWT = NT / WN;
    constexpr int MFRAG = MW / 16, NFRAG = NWT / 8;
    extern __shared__ char gsm[];

    const int tid = threadIdx.x, wid = tid >> 5, lane = tid & 31;
    const int bm = blockIdx.y * 128, bn = blockIdx.x * NT, dir = blockIdx.z;
    const int wm = (wid / WN) * MW, wn = (wid % WN) * NWT;
    const bf16* Whi = dir ? Whi1 : Whi0;
    const bf16* Wlo = dir ? Wlo1 : Wlo0;
    const float* bias = dir ? bias1 : bias0;
    const int cofs = dir * coff;
    const u32 sb = smem_u32(gsm);

    float acc[MFRAG][NFRAG][4];
    #pragma unroll
    for (int i = 0; i < MFRAG; i++)
        #pragma unroll
        for (int j = 0; j < NFRAG; j++)
            #pragma unroll
            for (int q = 0; q < 4; q++) acc[i][j][q] = 0.f;

    g2s_chunk<NT>(sb, Ahi, Alo, Whi, Wlo, bm, bn, 0, K, Nw, tid);
    asm volatile("cp.async.commit_group;" ::: "memory");

    const int nch = K / 32;
    for (int ch = 0; ch < nch; ch++) {
        asm volatile("cp.async.wait_group 0;" ::: "memory");
        __syncthreads();
        const u32 s0 = sb + (u32)(ch & 1) * STG;
        if (ch + 1 < nch) {
            g2s_chunk<NT>(sb + (u32)((ch + 1) & 1) * STG, Ahi, Alo, Whi, Wlo,
                          bm, bn, (ch + 1) * 32, K, Nw, tid);
            asm volatile("cp.async.commit_group;" ::: "memory");
        }
        const u32 saH = s0, saL = s0 + ASZ, swH = s0 + 2 * ASZ, swL = swH + WSZ;
        #pragma unroll
        for (int s = 0; s < 2; s++) {
            u32 wh[NFRAG][2], wl[NFRAG][2];
            #pragma unroll
            for (int np = 0; np < NFRAG / 2; np++) {
                u32 r0, r1, r2, r3;
                const u32 colb = 2 * (u32)(wn + np * 16 + ((lane >> 4) << 3));
                const u32 rowb = (u32)(s * 16 + (lane & 15)) * PB;
                ldsm4t(r0, r1, r2, r3, swH + rowb + colb);
                wh[2*np][0] = r0; wh[2*np][1] = r1;
                wh[2*np+1][0] = r2; wh[2*np+1][1] = r3;
                ldsm4t(r0, r1, r2, r3, swL + rowb + colb);
                wl[2*np][0] = r0; wl[2*np][1] = r1;
                wl[2*np+1][0] = r2; wl[2*np+1][1] = r3;
            }
            u32 a[MFRAG][4];
            #pragma unroll
            for (int mf = 0; mf < MFRAG; mf++)
                ldsm4(a[mf][0], a[mf][1], a[mf][2], a[mf][3],
                      saH + (u32)(wm + mf * 16 + (lane & 15)) * PA
                          + s * 32 + ((lane >> 4) << 4));
            #pragma unroll
            for (int mf = 0; mf < MFRAG; mf++)
                #pragma unroll
                for (int nf = 0; nf < NFRAG; nf++) {
                    mma_bf16(acc[mf][nf], a[mf], wh[nf]);
                    mma_bf16(acc[mf][nf], a[mf], wl[nf]);
                }
            #pragma unroll
            for (int mf = 0; mf < MFRAG; mf++)
                ldsm4(a[mf][0], a[mf][1], a[mf][2], a[mf][3],
                      saL + (u32)(wm + mf * 16 + (lane & 15)) * PA
                          + s * 32 + ((lane >> 4) << 4));
            #pragma unroll
            for (int mf = 0; mf < MFRAG; mf++)
                #pragma unroll
                for (int nf = 0; nf < NFRAG; nf++)
                    mma_bf16(acc[mf][nf], a[mf], wh[nf]);
        }
        __syncthreads();
    }

    #pragma unroll
    for (int mf = 0; mf < MFRAG; mf++) {
        #pragma unroll
        for (int nf = 0; nf < NFRAG; nf++) {
            const int r0 = bm + wm + mf * 16 + (lane >> 2);
            const int col = bn + wn + nf * 8 + (lane & 3) * 2;
            const float b0 = bias[col], b1 = bias[col + 1];
            *(float2*)&C[(size_t)r0 * ldc + cofs + col] =
                make_float2(acc[mf][nf][0] + b0, acc[mf][nf][1] + b1);
            *(float2*)&C[(size_t)(r0 + 8) * ldc + cofs + col] =
                make_float2(acc[mf][nf][2] + b0, acc[mf][nf][3] + b1);
        }
    }
}

// ---------------------------------------------------------------------------
// Tensor-core LSTM v2: gate-interleaved columns (col = j*4+g), in-register
// epilogue via shfl, register c state, double-buffered h, ONE barrier/step.
// ---------------------------------------------------------------------------
template<int HU, int KLO, bool SEQ>
__global__ __launch_bounds__(512, 1)
void lstm_tc2(const float* __restrict__ xz, size_t strideB, size_t strideT,
              const float* __restrict__ Uf, const float* __restrict__ Ub,
              bf16* __restrict__ ohi, bf16* __restrict__ olo, int ldo, int T)
{
    constexpr int NG = 4 * HU, NW = NG / 16, NFRAG = NW / 8;
    constexpr int KF = HU / 16, NFG = NG / 8;
    constexpr int HP = HU + 8;
    constexpr int HB = 16 * HP;            // halves per buffer

    extern __shared__ char sm[];
    u64*    Uhi = (u64*)sm;                         // [KF*NFG*32]
    u64*    Ulo = Uhi + KF * NFG * 32;              // [KLO*NFG*32]
    __half* hh  = (__half*)(Ulo + KLO * NFG * 32);  // [2][HB]
    __half* hl  = hh + 2 * HB;                      // [2][HB]

    const int tid = threadIdx.x, wid = tid >> 5, lane = tid & 31;
    const int g = lane >> 2, c2 = (lane & 3) * 2;
    const int dir = blockIdx.y, b0 = blockIdx.x * 16;
    const float* U   = dir ? Ub : Uf;
    const float* xzd = xz + (size_t)dir * NG;
    bf16* ohid = ohi + dir * HU;
    bf16* olid = olo + dir * HU;

    // U -> fragment-linear f16, permuted columns
    for (int idx = tid; idx < KF * NFG * 32; idx += 512) {
        int ln = idx & 31, fr = idx >> 5;
        int nfg = fr % NFG, kf = fr / NFG;
        int n = nfg * 8 + (ln >> 2);
        int oc = (n & 3) * HU + (n >> 2);
        int k0 = kf * 16 + 2 * (ln & 3);
        float x0 = U[(size_t)k0 * NG + oc],       x1 = U[(size_t)(k0 + 1) * NG + oc];
        float x2 = U[(size_t)(k0 + 8) * NG + oc], x3 = U[(size_t)(k0 + 9) * NG + oc];
        Uhi[idx] = pkh64(__half2float(__float2half_rn(x0)),
                         __half2float(__float2half_rn(x1)),
                         __half2float(__float2half_rn(x2)),
                         __half2float(__float2half_rn(x3)));
        if (kf < KLO)
            Ulo[(size_t)(kf * NFG + nfg) * 32 + ln] =
                pkh64(hres(x0), hres(x1), hres(x2), hres(x3));
    }
    {   // zero both h buffers (hh and hl are contiguous: 4*HB halves)
        u32* z = (u32*)hh;
        for (int idx = tid; idx < 2 * HB; idx += 512) z[idx] = 0;
    }
    __syncthreads();

    float cst[NFRAG][2];
    #pragma unroll
    for (int i = 0; i < NFRAG; i++) { cst[i][0] = 0.f; cst[i][1] = 0.f; }
    int cur = 0;
    const int p = lane & 1;
    const int jl = (lane >> 1) & 1;

    for (int t = 0; t < T; t++) {
        const int tt = dir ? (T - 1 - t) : t;

        float xv[NFRAG][4];
        {
            const float* xp0 = xzd + (size_t)(b0 + g) * strideB
                               + (size_t)tt * strideT + wid * NW + c2;
            const float* xp1 = xp0 + 8 * strideB;
            #pragma unroll
            for (int nf = 0; nf < NFRAG; nf++) {
                float2 v0 = *(const float2*)(xp0 + nf * 8);
                float2 v1 = *(const float2*)(xp1 + nf * 8);
                xv[nf][0] = v0.x; xv[nf][1] = v0.y;
                xv[nf][2] = v1.x; xv[nf][3] = v1.y;
            }
        }

        float acc[NFRAG][4];
        #pragma unroll
        for (int nf = 0; nf < NFRAG; nf++)
            #pragma unroll
            for (int q = 0; q < 4; q++) acc[nf][q] = 0.f;

        const __half* hhc = hh + cur * HB;
        const __half* hlc = hl + cur * HB;
        #pragma unroll
        for (int kf = 0; kf < KF; kf++) {
            const int kb = kf * 16 + c2;
            u32 a[4], al[4];
            a[0]  = *(const u32*)&hhc[g * HP + kb];
            a[1]  = *(const u32*)&hhc[(g + 8) * HP + kb];
            a[2]  = *(const u32*)&hhc[g * HP + kb + 8];
            a[3]  = *(const u32*)&hhc[(g + 8) * HP + kb + 8];
            al[0] = *(const u32*)&hlc[g * HP + kb];
            al[1] = *(const u32*)&hlc[(g + 8) * HP + kb];
            al[2] = *(const u32*)&hlc[g * HP + kb + 8];
            al[3] = *(const u32*)&hlc[(g + 8) * HP + kb + 8];
            const u64* ub = Uhi + ((size_t)kf * NFG + wid * NFRAG) * 32 + lane;
            #pragma unroll
            for (int nf = 0; nf < NFRAG; nf++) {
                u64 b = ub[nf * 32];
                mma_f16(acc[nf], a,  (u32)b, (u32)(b >> 32));
                mma_f16(acc[nf], al, (u32)b, (u32)(b >> 32));
            }
            if (kf < KLO) {
                const u64* lb = Ulo + ((size_t)kf * NFG + wid * NFRAG) * 32 + lane;
                #pragma unroll
                for (int nf = 0; nf < NFRAG; nf++) {
                    u64 b = lb[nf * 32];
                    mma_f16(acc[nf], a, (u32)b, (u32)(b >> 32));
                }
            }
        }

        // epilogue: fragment holds (i,f)/(g,o) pairs; shfl-combine; reg c.
        __half* hhn = hh + (cur ^ 1) * HB;
        __half* hln = hl + (cur ^ 1) * HB;
        #pragma unroll
        for (int nf = 0; nf < NFRAG; nf++) {
            float z0 = acc[nf][0] + xv[nf][0];
            float z1 = acc[nf][1] + xv[nf][1];
            float z2 = acc[nf][2] + xv[nf][2];
            float z3 = acc[nf][3] + xv[nf][3];
            float a0 = p ? fmaxf(z0, 0.f) : sigm(z0);
            float a1 = sigm(z1);
            float a2 = p ? fmaxf(z2, 0.f) : sigm(z2);
            float a3 = sigm(z3);
            float q0 = __shfl_xor_sync(0xFFFFFFFFu, a0, 1);
            float q1 = __shfl_xor_sync(0xFFFFFFFFu, a1, 1);
            float q2 = __shfl_xor_sync(0xFFFFFFFFu, a2, 1);
            float q3 = __shfl_xor_sync(0xFFFFFFFFu, a3, 1);
            if (!p) {   // i=a0, f=a1, g=q0, o=q1 (rows g and g+8)
                float c0 = a1 * cst[nf][0] + a0 * q0; cst[nf][0] = c0;
                float h0 = q1 * fmaxf(c0, 0.f);
                float c1 = a3 * cst[nf][1] + a2 * q2; cst[nf][1] = c1;
                float h1 = q3 * fmaxf(c1, 0.f);
                const int jw = wid * (NW / 4) + nf * 2 + jl;
                __half f0 = __float2half_rn(h0);
                __half f1 = __float2half_rn(h1);
                hhn[g * HP + jw]       = f0;
                hln[g * HP + jw]       = __float2half_rn(h0 - __half2float(f0));
                hhn[(g + 8) * HP + jw] = f1;
                hln[(g + 8) * HP + jw] = __float2half_rn(h1 - __half2float(f1));
                if (SEQ || t == T - 1) {
                    size_t i0 = SEQ ? (((size_t)(b0 + g) * T + tt) * ldo + jw)
                                    : ((size_t)(b0 + g) * ldo + jw);
                    size_t i1 = SEQ ? (((size_t)(b0 + g + 8) * T + tt) * ldo + jw)
                                    : ((size_t)(b0 + g + 8) * ldo + jw);
                    bf16 w0 = __float2bfloat16_rn(h0);
                    bf16 w1 = __float2bfloat16_rn(h1);
                    ohid[i0] = w0;
                    olid[i0] = __float2bfloat16_rn(h0 - __bfloat162float(w0));
                    ohid[i1] = w1;
                    olid[i1] = __float2bfloat16_rn(h1 - __bfloat162float(w1));
                }
            }
        }
        __syncthreads();
        cur ^= 1;
    }
}

// ---------------------------------------------------------------------------
extern "C" void kernel_launch(void* const* d_in, const int* in_sizes, int n_in,
                              void* d_out, int out_size)
{
    const float* x    = (const float*)d_in[0];
    const float* e1fW = (const float*)d_in[1];
    const float* e1fU = (const float*)d_in[2];
    const float* e1fb = (const float*)d_in[3];
    const float* e1bW = (const float*)d_in[4];
    const float* e1bU = (const float*)d_in[5];
    const float* e1bb = (const float*)d_in[6];
    const float* e2fW = (const float*)d_in[7];
    const float* e2fU = (const float*)d_in[8];
    const float* e2fb = (const float*)d_in[9];
    const float* e2bW = (const float*)d_in[10];
    const float* e2bU = (const float*)d_in[11];
    const float* e2bb = (const float*)d_in[12];
    const float* d1fW = (const float*)d_in[13];
    const float* d1fU = (const float*)d_in[14];
    const float* d1fb = (const float*)d_in[15];
    const float* d1bW = (const float*)d_in[16];
    const float* d1bU = (const float*)d_in[17];
    const float* d1bb = (const float*)d_in[18];
    const float* d2fW = (const float*)d_in[19];
    const float* d2fU = (const float*)d_in[20];
    const float* d2fb = (const float*)d_in[21];
    const float* d2bW = (const float*)d_in[22];
    const float* d2bU = (const float*)d_in[23];
    const float* d2bb = (const float*)d_in[24];
    const float* Wd   = (const float*)d_in[25];
    const float* bd   = (const float*)d_in[26];

    float *xz1, *xz2, *xzd1, *bp;
    bf16 *xhi, *xlo, *h1hi, *h1lo, *hd1hi, *hd1lo, *zhi, *zlo, *whi, *wlo;
    cudaGetSymbolAddress((void**)&xz1,   g_xz1);
    cudaGetSymbolAddress((void**)&xz2,   g_xz2);
    cudaGetSymbolAddress((void**)&xzd1,  g_xzd1);
    cudaGetSymbolAddress((void**)&bp,    g_bp);
    cudaGetSymbolAddress((void**)&xhi,   g_xhi);
    cudaGetSymbolAddress((void**)&xlo,   g_xlo);
    cudaGetSymbolAddress((void**)&h1hi,  g_h1hi);
    cudaGetSymbolAddress((void**)&h1lo,  g_h1lo);
    cudaGetSymbolAddress((void**)&hd1hi, g_hd1hi);
    cudaGetSymbolAddress((void**)&hd1lo, g_hd1lo);
    cudaGetSymbolAddress((void**)&zhi,   g_zhi);
    cudaGetSymbolAddress((void**)&zlo,   g_zlo);
    cudaGetSymbolAddress((void**)&whi,   g_whi);
    cudaGetSymbolAddress((void**)&wlo,   g_wlo);

    const int O_e1f = 0,      O_e1b = 32768,  O_e2f = 65536,  O_e2b = 131072;
    const int O_d1f = 196608, O_d1b = 229376, O_d2f = 262144, O_d2b = 327680;
    const int O_wd  = 393216;
    const int B_e1f = 0, B_e1b = 512, B_e2f = 1024, B_e2b = 1280;
    const int B_d1f = 1536, B_d1b = 1792, B_d2f = 2048, B_d2b = 2560;

    // lstm smem: HU=128,KLO=0: 131072 + 4*16*136*2 = 148480
    //            HU=64, KLO=4: 32768+32768 + 4*16*72*2 = 74752
    const int LS128 = 131072 + 4 * 16 * 136 * 2;
    const int LS64  = 65536 + 4 * 16 * 72 * 2;
    cudaFuncSetAttribute(lstm_tc2<128, 0, true>,
                         cudaFuncAttributeMaxDynamicSharedMemorySize, LS128);
    cudaFuncSetAttribute(lstm_tc2<64, 4, false>,
                         cudaFuncAttributeMaxDynamicSharedMemorySize, LS64);
    cudaFuncSetAttribute(lstm_tc2<64, 4, true>,
                         cudaFuncAttributeMaxDynamicSharedMemorySize, LS64);

    const int GS128 = 2 * (2 * 128 * 80 + 2 * 32 * 272);
    const int GS64  = 2 * (2 * 128 * 80 + 2 * 32 * 144);
    cudaFuncSetAttribute(hgemm2<128, 2, 4>,
                         cudaFuncAttributeMaxDynamicSharedMemorySize, GS128);
    cudaFuncSetAttribute(hgemm2<64, 4, 2>,
                         cudaFuncAttributeMaxDynamicSharedMemorySize, GS64);

    const int T = 256;

    cvt_x<<<2048, 256>>>(x, xhi, xlo, 2097152);
    cvt_x<<<64, 256>>>(Wd, whi + O_wd, wlo + O_wd, 4096);
    cvt_wperm<<<dim3(64, 8), 256>>>(e1fW, e1bW, e2fW, e2bW,
                                    d1fW, d1bW, d2fW, d2bW, whi, wlo);
    cvt_bperm<<<dim3(1, 8), 512>>>(e1fb, e1bb, e2fb, e2bb,
                                   d1fb, d1bb, d2fb, d2bb, bp);

    // e1 (K=64, Nw=512, both dirs)
    hgemm2<128, 2, 4><<<dim3(4, 1024, 2), 256, GS128>>>(
        xhi, xlo, whi + O_e1f, wlo + O_e1f, whi + O_e1b, wlo + O_e1b,
        bp + B_e1f, bp + B_e1b, xz1, 64, 512, 1024, 512);
    lstm_tc2<128, 0, true><<<dim3(32, 2), 512, LS128>>>(
        xz1, (size_t)T * 1024, 1024, e1fU, e1bU, h1hi, h1lo, 256, T);

    // e2 (K=256, Nw=256)
    hgemm2<128, 2, 4><<<dim3(2, 1024, 2), 256, GS128>>>(
        h1hi, h1lo, whi + O_e2f, wlo + O_e2f, whi + O_e2b, wlo + O_e2b,
        bp + B_e2f, bp + B_e2b, xz2, 256, 256, 512, 256);
    lstm_tc2<64, 4, false><<<dim3(32, 2), 512, LS64>>>(
        xz2, (size_t)T * 512, 512, e2fU, e2bU, zhi, zlo, 128, T);

    // d1 (M=512, K=128, Nw=256)
    hgemm2<128, 2, 4><<<dim3(2, 4, 2), 256, GS128>>>(
        zhi, zlo, whi + O_d1f, wlo + O_d1f, whi + O_d1b, wlo + O_d1b,
        bp + B_d1f, bp + B_d1b, xzd1, 128, 256, 512, 256);
    lstm_tc2<64, 4, true><<<dim3(32, 2), 512, LS64>>>(
        xzd1, 512, 0, d1fU, d1bU, hd1hi, hd1lo, 128, T);

    // d2 (K=128, Nw=512)
    hgemm2<128, 2, 4><<<dim3(4, 1024, 2), 256, GS128>>>(
        hd1hi, hd1lo, whi + O_d2f, wlo + O_d2f, whi + O_d2b, wlo + O_d2b,
        bp + B_d2f, bp + B_d2b, xz1, 128, 512, 1024, 512);
    lstm_tc2<128, 0, true><<<dim3(32, 2), 512, LS128>>>(
        xz1, (size_t)T * 1024, 1024, d2fU, d2bU, h1hi, h1lo, 256, T);

    // dense (K=256, Nw=64, single dir, unpermuted)
    hgemm2<64, 4, 2><<<dim3(1, 1024, 1), 256, GS64>>>(
        h1hi, h1lo, whi + O_wd, wlo + O_wd, whi + O_wd, wlo + O_wd,
        bd, bd, (float*)d_out, 256, 64, 64, 0);
}

// round 13
// speedup vs baseline: 1.4005x; 1.4005x over previous
#include <cuda_runtime.h>
#include <cuda_bf16.h>
#include <cuda_fp16.h>
#include <math.h>
#include <stdint.h>

#define BT 131072
typedef unsigned long long u64;
typedef unsigned int u32;
typedef __nv_bfloat16 bf16;

// fp32 scratch
__device__ float g_xz1 [134217728];   // [BT,1024]
__device__ float g_xz2 [67108864];    // [BT, 512]
__device__ float g_xzd1[262144];      // [B, 512]
// bf16 hi/lo planes
__device__ bf16 g_xhi  [8388608],  g_xlo  [8388608];
__device__ bf16 g_h1hi [33554432], g_h1lo [33554432];
__device__ bf16 g_hd1hi[16777216], g_hd1lo[16777216];
__device__ bf16 g_zhi  [65536],    g_zlo  [65536];
__device__ bf16 g_whi  [409600],   g_wlo  [409600];

__device__ __forceinline__ float sigm(float x) {
    return __fdividef(1.0f, 1.0f + __expf(-x));
}
__device__ __forceinline__ u32 smem_u32(const void* p) {
    u32 a; asm("{ .reg .u64 t; cvta.to.shared.u64 t, %1; cvt.u32.u64 %0, t; }"
               : "=r"(a) : "l"(p));
    return a;
}
__device__ __forceinline__ u32 pkbf(float a, float b) {
    __nv_bfloat162 t = __floats2bfloat162_rn(a, b);
    return *reinterpret_cast<u32*>(&t);
}
__device__ __forceinline__ float bres(float x) {
    return x - __bfloat162float(__float2bfloat16_rn(x));
}
__device__ __forceinline__ u32 pkh2(float a, float b) {
    __half2 h = __floats2half2_rn(a, b);
    return *reinterpret_cast<u32*>(&h);
}
__device__ __forceinline__ u64 pkh64(float a, float b, float c, float d) {
    return (u64)pkh2(a, b) | ((u64)pkh2(c, d) << 32);
}
__device__ __forceinline__ void ldsm4(u32 &r0, u32 &r1, u32 &r2, u32 &r3, u32 a) {
    asm volatile("ldmatrix.sync.aligned.m8n8.x4.shared.b16 {%0,%1,%2,%3}, [%4];"
                 : "=r"(r0), "=r"(r1), "=r"(r2), "=r"(r3) : "r"(a));
}
__device__ __forceinline__ void ldsm4t(u32 &r0, u32 &r1, u32 &r2, u32 &r3, u32 a) {
    asm volatile("ldmatrix.sync.aligned.m8n8.x4.trans.shared.b16 {%0,%1,%2,%3}, [%4];"
                 : "=r"(r0), "=r"(r1), "=r"(r2), "=r"(r3) : "r"(a));
}
__device__ __forceinline__ void mma_bf16(float* c, const u32* a, const u32* b) {
    asm volatile("mma.sync.aligned.m16n8k16.row.col.f32.bf16.bf16.f32 "
                 "{%0,%1,%2,%3}, {%4,%5,%6,%7}, {%8,%9}, {%0,%1,%2,%3};"
                 : "+f"(c[0]), "+f"(c[1]), "+f"(c[2]), "+f"(c[3])
                 : "r"(a[0]), "r"(a[1]), "r"(a[2]), "r"(a[3]), "r"(b[0]), "r"(b[1]));
}
__device__ __forceinline__ void mma_f16(float* c, const u32* a, u32 b0, u32 b1) {
    asm volatile("mma.sync.aligned.m16n8k16.row.col.f32.f16.f16.f32 "
                 "{%0,%1,%2,%3}, {%4,%5,%6,%7}, {%8,%9}, {%0,%1,%2,%3};"
                 : "+f"(c[0]), "+f"(c[1]), "+f"(c[2]), "+f"(c[3])
                 : "r"(a[0]), "r"(a[1]), "r"(a[2]), "r"(a[3]), "r"(b0), "r"(b1));
}
__device__ __forceinline__ void cp8(u32 d, const void* s) {
    asm volatile("cp.async.ca.shared.global [%0], [%1], 8;" :: "r"(d), "l"(s));
}
__device__ __forceinline__ void cp16(u32 d, const void* s) {
    asm volatile("cp.async.ca.shared.global [%0], [%1], 16;" :: "r"(d), "l"(s));
}

// ---------------------------------------------------------------------------
// Converters (R11, proven)
// ---------------------------------------------------------------------------
__global__ void cvt_x(const float* __restrict__ s, bf16* __restrict__ hi,
                      bf16* __restrict__ lo, int n4)
{
    for (int i = blockIdx.x * blockDim.x + threadIdx.x; i < n4;
         i += gridDim.x * blockDim.x) {
        float4 v = ((const float4*)s)[i];
        ((uint2*)hi)[i] = make_uint2(pkbf(v.x, v.y), pkbf(v.z, v.w));
        ((uint2*)lo)[i] = make_uint2(pkbf(bres(v.x), bres(v.y)),
                                     pkbf(bres(v.z), bres(v.w)));
    }
}

__global__ void cvt_w9(const float* w0, const float* w1, const float* w2,
                       const float* w3, const float* w4, const float* w5,
                       const float* w6, const float* w7, const float* w8,
                       bf16* __restrict__ hi, bf16* __restrict__ lo)
{
    const int off[10] = {0, 8192, 16384, 32768, 49152, 57344,
                         65536, 81920, 98304, 102400};   // float4 units
    const float* ws[9] = {w0, w1, w2, w3, w4, w5, w6, w7, w8};
    for (int i = blockIdx.x * blockDim.x + threadIdx.x; i < 102400;
         i += gridDim.x * blockDim.x) {
        int s = 0;
        #pragma unroll
        for (int k = 1; k < 9; k++) if (i >= off[k]) s = k;
        float4 v = ((const float4*)ws[s])[i - off[s]];
        ((uint2*)hi)[i] = make_uint2(pkbf(v.x, v.y), pkbf(v.z, v.w));
        ((uint2*)lo)[i] = make_uint2(pkbf(bres(v.x), bres(v.y)),
                                     pkbf(bres(v.z), bres(v.w)));
    }
}

// ---------------------------------------------------------------------------
// hgemm2 (R11, proven): C = A@W + bias, pre-split bf16 planes, cp.async.
// ---------------------------------------------------------------------------
template<int NT>
__device__ __forceinline__ void g2s_chunk(
    u32 sbase, const bf16* Ahi, const bf16* Alo,
    const bf16* Whi, const bf16* Wlo,
    int bm, int bn, int k0, int K, int Nw, int tid)
{
    constexpr int PA = 80, ASZ = 128 * PA;
    constexpr int PB = NT * 2 + 16, WSZ = 32 * PB;
    constexpr int WOPS = NT / 32;
    {
        int row = tid & 127;
        const bf16* src = ((tid & 128) ? Alo : Ahi) + (size_t)(bm + row) * K + k0;
        u32 dst = sbase + ((tid & 128) ? ASZ : 0) + row * PA;
        #pragma unroll
        for (int i = 0; i < 8; i++)
            cp8(dst + i * 8, (const char*)src + i * 8);
    }
    {
        int idx = tid & 127, row = idx >> 2, seg = idx & 3;
        const bf16* src = ((tid & 128) ? Wlo : Whi)
                          + (size_t)(k0 + row) * Nw + bn + seg * (NT / 4);
        u32 dst = sbase + 2 * ASZ + ((tid & 128) ? WSZ : 0) + row * PB + seg * (NT / 2);
        #pragma unroll
        for (int i = 0; i < WOPS; i++)
            cp16(dst + i * 16, (const char*)src + i * 16);
    }
}

template<int NT, int WM, int WN>
__global__ __launch_bounds__(256, 2)
void hgemm2(const bf16* __restrict__ Ahi, const bf16* __restrict__ Alo,
            const bf16* __restrict__ Whi0, const bf16* __restrict__ Wlo0,
            const bf16* __restrict__ Whi1, const bf16* __restrict__ Wlo1,
            const float* __restrict__ bias0, const float* __restrict__ bias1,
            float* __restrict__ C, int K, int Nw, int ldc, int coff)
{
    constexpr int PA = 80, ASZ = 128 * PA;
    constexpr int PB = NT * 2 + 16, WSZ = 32 * PB;
    constexpr int STG = 2 * ASZ + 2 * WSZ;
    constexpr int MW = 128 / WM, NWT = NT / WN;
    constexpr int MFRAG = MW / 16, NFRAG = NWT / 8;
    extern __shared__ char gsm[];

    const int tid = threadIdx.x, wid = tid >> 5, lane = tid & 31;
    const int bm = blockIdx.y * 128, bn = blockIdx.x * NT, dir = blockIdx.z;
    const int wm = (wid / WN) * MW, wn = (wid % WN) * NWT;
    const bf16* Whi = dir ? Whi1 : Whi0;
    const bf16* Wlo = dir ? Wlo1 : Wlo0;
    const float* bias = dir ? bias1 : bias0;
    const int cofs = dir * coff;
    const u32 sb = smem_u32(gsm);

    float acc[MFRAG][NFRAG][4];
    #pragma unroll
    for (int i = 0; i < MFRAG; i++)
        #pragma unroll
        for (int j = 0; j < NFRAG; j++)
            #pragma unroll
            for (int q = 0; q < 4; q++) acc[i][j][q] = 0.f;

    g2s_chunk<NT>(sb, Ahi, Alo, Whi, Wlo, bm, bn, 0, K, Nw, tid);
    asm volatile("cp.async.commit_group;" ::: "memory");

    const int nch = K / 32;
    for (int ch = 0; ch < nch; ch++) {
        asm volatile("cp.async.wait_group 0;" ::: "memory");
        __syncthreads();
        const u32 s0 = sb + (u32)(ch & 1) * STG;
        if (ch + 1 < nch) {
            g2s_chunk<NT>(sb + (u32)((ch + 1) & 1) * STG, Ahi, Alo, Whi, Wlo,
                          bm, bn, (ch + 1) * 32, K, Nw, tid);
            asm volatile("cp.async.commit_group;" ::: "memory");
        }
        const u32 saH = s0, saL = s0 + ASZ, swH = s0 + 2 * ASZ, swL = swH + WSZ;
        #pragma unroll
        for (int s = 0; s < 2; s++) {
            u32 wh[NFRAG][2], wl[NFRAG][2];
            #pragma unroll
            for (int np = 0; np < NFRAG / 2; np++) {
                u32 r0, r1, r2, r3;
                const u32 colb = 2 * (u32)(wn + np * 16 + ((lane >> 4) << 3));
                const u32 rowb = (u32)(s * 16 + (lane & 15)) * PB;
                ldsm4t(r0, r1, r2, r3, swH + rowb + colb);
                wh[2*np][0] = r0; wh[2*np][1] = r1;
                wh[2*np+1][0] = r2; wh[2*np+1][1] = r3;
                ldsm4t(r0, r1, r2, r3, swL + rowb + colb);
                wl[2*np][0] = r0; wl[2*np][1] = r1;
                wl[2*np+1][0] = r2; wl[2*np+1][1] = r3;
            }
            u32 a[MFRAG][4];
            #pragma unroll
            for (int mf = 0; mf < MFRAG; mf++)
                ldsm4(a[mf][0], a[mf][1], a[mf][2], a[mf][3],
                      saH + (u32)(wm + mf * 16 + (lane & 15)) * PA
                          + s * 32 + ((lane >> 4) << 4));
            #pragma unroll
            for (int mf = 0; mf < MFRAG; mf++)
                #pragma unroll
                for (int nf = 0; nf < NFRAG; nf++) {
                    mma_bf16(acc[mf][nf], a[mf], wh[nf]);
                    mma_bf16(acc[mf][nf], a[mf], wl[nf]);
                }
            #pragma unroll
            for (int mf = 0; mf < MFRAG; mf++)
                ldsm4(a[mf][0], a[mf][1], a[mf][2], a[mf][3],
                      saL + (u32)(wm + mf * 16 + (lane & 15)) * PA
                          + s * 32 + ((lane >> 4) << 4));
            #pragma unroll
            for (int mf = 0; mf < MFRAG; mf++)
                #pragma unroll
                for (int nf = 0; nf < NFRAG; nf++)
                    mma_bf16(acc[mf][nf], a[mf], wh[nf]);
        }
        __syncthreads();
    }

    #pragma unroll
    for (int mf = 0; mf < MFRAG; mf++) {
        #pragma unroll
        for (int nf = 0; nf < NFRAG; nf++) {
            const int r0 = bm + wm + mf * 16 + (lane >> 2);
            const int col = bn + wn + nf * 8 + (lane & 3) * 2;
            const float b0 = bias[col], b1 = bias[col + 1];
            *(float2*)&C[(size_t)r0 * ldc + cofs + col] =
                make_float2(acc[mf][nf][0] + b0, acc[mf][nf][1] + b1);
            *(float2*)&C[(size_t)(r0 + 8) * ldc + cofs + col] =
                make_float2(acc[mf][nf][2] + b0, acc[mf][nf][3] + b1);
        }
    }
}

// ---------------------------------------------------------------------------
// Tensor-core LSTM v3 = R11 structure, SINGLE-TERM f16 recurrence:
// acc = h_f16 @ U_f16 only (h_lo and U_lo terms dropped — 2.25x fewer mma).
// ---------------------------------------------------------------------------
template<int HU, bool SEQ>
__global__ __launch_bounds__(512, 1)
void lstm_tc(const float* __restrict__ xz, size_t strideB, size_t strideT,
             const float* __restrict__ Uf, const float* __restrict__ Ub,
             bf16* __restrict__ ohi, bf16* __restrict__ olo, int ldo, int T)
{
    constexpr int NG = 4 * HU, NW = NG / 16, NFRAG = NW / 8;
    constexpr int KF = HU / 16, NFG = NG / 8;
    constexpr int HP = HU + 8;
    constexpr int GP = NG + 4;
    constexpr int NC = HU / 32;

    extern __shared__ char sm[];
    u64*    Uhi  = (u64*)sm;                        // [KF*NFG*32]
    __half* hhi  = (__half*)(Uhi + KF * NFG * 32);  // [16*HP]
    float*  gbuf = (float*)(hhi + 16 * HP);         // [16*GP]

    const int tid = threadIdx.x, wid = tid >> 5, lane = tid & 31;
    const int g = lane >> 2, c2 = (lane & 3) * 2;
    const int dir = blockIdx.y, b0 = blockIdx.x * 16;
    const float* U   = dir ? Ub : Uf;
    const float* xzd = xz + (size_t)dir * NG;
    bf16* ohid = ohi + dir * HU;
    bf16* olid = olo + dir * HU;

    for (int idx = tid; idx < KF * NFG * 32; idx += 512) {
        int ln = idx & 31, fr = idx >> 5;
        int nfg = fr % NFG, kf = fr / NFG;
        int n = nfg * 8 + (ln >> 2);
        int k0 = kf * 16 + 2 * (ln & 3);
        float x0 = U[(size_t)k0 * NG + n],       x1 = U[(size_t)(k0 + 1) * NG + n];
        float x2 = U[(size_t)(k0 + 8) * NG + n], x3 = U[(size_t)(k0 + 9) * NG + n];
        Uhi[idx] = pkh64(__half2float(__float2half_rn(x0)),
                         __half2float(__float2half_rn(x1)),
                         __half2float(__float2half_rn(x2)),
                         __half2float(__float2half_rn(x3)));
    }
    for (int idx = tid; idx < 16 * HP / 2; idx += 512)
        ((u32*)hhi)[idx] = 0;
    __syncthreads();

    const int gate = (wid * NW) / HU;
    const int ur = tid >> 5, uj = (tid & 31) * NC;
    float cst[NC];
    #pragma unroll
    for (int i = 0; i < NC; i++) cst[i] = 0.f;

    for (int t = 0; t < T; t++) {
        const int tt = dir ? (T - 1 - t) : t;

        float xv[NFRAG][4];
        {
            const float* xp0 = xzd + (size_t)(b0 + g) * strideB
                               + (size_t)tt * strideT + wid * NW + c2;
            const float* xp1 = xp0 + 8 * strideB;
            #pragma unroll
            for (int nf = 0; nf < NFRAG; nf++) {
                float2 v0 = *(const float2*)(xp0 + nf * 8);
                float2 v1 = *(const float2*)(xp1 + nf * 8);
                xv[nf][0] = v0.x; xv[nf][1] = v0.y;
                xv[nf][2] = v1.x; xv[nf][3] = v1.y;
            }
        }

        float acc[NFRAG][4];
        #pragma unroll
        for (int nf = 0; nf < NFRAG; nf++)
            #pragma unroll
            for (int q = 0; q < 4; q++) acc[nf][q] = 0.f;

        #pragma unroll
        for (int kf = 0; kf < KF; kf++) {
            const int kb = kf * 16 + c2;
            u32 a[4];
            a[0] = *(const u32*)&hhi[g * HP + kb];
            a[1] = *(const u32*)&hhi[(g + 8) * HP + kb];
            a[2] = *(const u32*)&hhi[g * HP + kb + 8];
            a[3] = *(const u32*)&hhi[(g + 8) * HP + kb + 8];
            const u64* ub = Uhi + ((size_t)kf * NFG + wid * NFRAG) * 32 + lane;
            #pragma unroll
            for (int nf = 0; nf < NFRAG; nf++) {
                u64 b = ub[nf * 32];
                mma_f16(acc[nf], a, (u32)b, (u32)(b >> 32));
            }
        }

        #pragma unroll
        for (int nf = 0; nf < NFRAG; nf++) {
            const int n = wid * NW + nf * 8 + c2;
            float z0 = acc[nf][0] + xv[nf][0], z1 = acc[nf][1] + xv[nf][1];
            float z2 = acc[nf][2] + xv[nf][2], z3 = acc[nf][3] + xv[nf][3];
            float2 w0, w1;
            if (gate == 2) {
                w0 = make_float2(fmaxf(z0, 0.f), fmaxf(z1, 0.f));
                w1 = make_float2(fmaxf(z2, 0.f), fmaxf(z3, 0.f));
            } else {
                w0 = make_float2(sigm(z0), sigm(z1));
                w1 = make_float2(sigm(z2), sigm(z3));
            }
            *(float2*)&gbuf[g * GP + n]       = w0;
            *(float2*)&gbuf[(g + 8) * GP + n] = w1;
        }
        __syncthreads();

        {
            float iv[NC], fv[NC], gv[NC], ov[NC], ho[NC];
            const float* gb = gbuf + ur * GP + uj;
            if constexpr (NC == 4) {
                *(float4*)iv = *(const float4*)(gb);
                *(float4*)fv = *(const float4*)(gb + HU);
                *(float4*)gv = *(const float4*)(gb + 2 * HU);
                *(float4*)ov = *(const float4*)(gb + 3 * HU);
            } else {
                *(float2*)iv = *(const float2*)(gb);
                *(float2*)fv = *(const float2*)(gb + HU);
                *(float2*)gv = *(const float2*)(gb + 2 * HU);
                *(float2*)ov = *(const float2*)(gb + 3 * HU);
            }
            #pragma unroll
            for (int i = 0; i < NC; i++) {
                cst[i] = fv[i] * cst[i] + iv[i] * gv[i];
                ho[i] = ov[i] * fmaxf(cst[i], 0.f);
            }
            if (SEQ || t == T - 1) {
                size_t idx = SEQ ? (((size_t)(b0 + ur) * T + tt) * ldo + uj)
                                 : ((size_t)(b0 + ur) * ldo + uj);
                u32 hw0 = pkbf(ho[0], ho[1]);
                u32 lw0 = pkbf(bres(ho[0]), bres(ho[1]));
                if constexpr (NC == 4) {
                    u32 hw1 = pkbf(ho[2], ho[3]);
                    u32 lw1 = pkbf(bres(ho[2]), bres(ho[3]));
                    *(uint2*)(ohid + idx) = make_uint2(hw0, hw1);
                    *(uint2*)(olid + idx) = make_uint2(lw0, lw1);
                } else {
                    *(u32*)(ohid + idx) = hw0;
                    *(u32*)(olid + idx) = lw0;
                }
            }
            u32 hw[NC / 2];
            #pragma unroll
            for (int q = 0; q < NC / 2; q++)
                hw[q] = pkh2(ho[2 * q], ho[2 * q + 1]);
            u32* hp = (u32*)&hhi[ur * HP + uj];
            if constexpr (NC == 4)
                *(uint2*)hp = make_uint2(hw[0], hw[1]);
            else
                hp[0] = hw[0];
        }
        __syncthreads();
    }
}

// ---------------------------------------------------------------------------
extern "C" void kernel_launch(void* const* d_in, const int* in_sizes, int n_in,
                              void* d_out, int out_size)
{
    const float* x    = (const float*)d_in[0];
    const float* e1fW = (const float*)d_in[1];
    const float* e1fU = (const float*)d_in[2];
    const float* e1fb = (const float*)d_in[3];
    const float* e1bW = (const float*)d_in[4];
    const float* e1bU = (const float*)d_in[5];
    const float* e1bb = (const float*)d_in[6];
    const float* e2fW = (const float*)d_in[7];
    const float* e2fU = (const float*)d_in[8];
    const float* e2fb = (const float*)d_in[9];
    const float* e2bW = (const float*)d_in[10];
    const float* e2bU = (const float*)d_in[11];
    const float* e2bb = (const float*)d_in[12];
    const float* d1fW = (const float*)d_in[13];
    const float* d1fU = (const float*)d_in[14];
    const float* d1fb = (const float*)d_in[15];
    const float* d1bW = (const float*)d_in[16];
    const float* d1bU = (const float*)d_in[17];
    const float* d1bb = (const float*)d_in[18];
    const float* d2fW = (const float*)d_in[19];
    const float* d2fU = (const float*)d_in[20];
    const float* d2fb = (const float*)d_in[21];
    const float* d2bW = (const float*)d_in[22];
    const float* d2bU = (const float*)d_in[23];
    const float* d2bb = (const float*)d_in[24];
    const float* Wd   = (const float*)d_in[25];
    const float* bd   = (const float*)d_in[26];

    float *xz1, *xz2, *xzd1;
    bf16 *xhi, *xlo, *h1hi, *h1lo, *hd1hi, *hd1lo, *zhi, *zlo, *whi, *wlo;
    cudaGetSymbolAddress((void**)&xz1,   g_xz1);
    cudaGetSymbolAddress((void**)&xz2,   g_xz2);
    cudaGetSymbolAddress((void**)&xzd1,  g_xzd1);
    cudaGetSymbolAddress((void**)&xhi,   g_xhi);
    cudaGetSymbolAddress((void**)&xlo,   g_xlo);
    cudaGetSymbolAddress((void**)&h1hi,  g_h1hi);
    cudaGetSymbolAddress((void**)&h1lo,  g_h1lo);
    cudaGetSymbolAddress((void**)&hd1hi, g_hd1hi);
    cudaGetSymbolAddress((void**)&hd1lo, g_hd1lo);
    cudaGetSymbolAddress((void**)&zhi,   g_zhi);
    cudaGetSymbolAddress((void**)&zlo,   g_zlo);
    cudaGetSymbolAddress((void**)&whi,   g_whi);
    cudaGetSymbolAddress((void**)&wlo,   g_wlo);

    const int O_e1f = 0,      O_e1b = 32768,  O_e2f = 65536,  O_e2b = 131072;
    const int O_d1f = 196608, O_d1b = 229376, O_d2f = 262144, O_d2b = 327680;
    const int O_wd  = 393216;

    // lstm smem: HU=128: 131072 + 16*136*2 + 16*516*4 = 168448
    //            HU=64 : 32768  + 16*72*2  + 16*260*4 = 51712
    const int LS128 = 131072 + 16 * 136 * 2 + 16 * 516 * 4;
    const int LS64  = 32768 + 16 * 72 * 2 + 16 * 260 * 4;
    cudaFuncSetAttribute(lstm_tc<128, true>,
                         cudaFuncAttributeMaxDynamicSharedMemorySize, LS128);
    cudaFuncSetAttribute(lstm_tc<64, false>,
                         cudaFuncAttributeMaxDynamicSharedMemorySize, LS64);
    cudaFuncSetAttribute(lstm_tc<64, true>,
                         cudaFuncAttributeMaxDynamicSharedMemorySize, LS64);

    const int GS128 = 2 * (2 * 128 * 80 + 2 * 32 * 272);
    const int GS64  = 2 * (2 * 128 * 80 + 2 * 32 * 144);
    cudaFuncSetAttribute(hgemm2<128, 2, 4>,
                         cudaFuncAttributeMaxDynamicSharedMemorySize, GS128);
    cudaFuncSetAttribute(hgemm2<64, 4, 2>,
                         cudaFuncAttributeMaxDynamicSharedMemorySize, GS64);

    const int T = 256;

    cvt_x<<<2048, 256>>>(x, xhi, xlo, 2097152);
    cvt_w9<<<256, 256>>>(e1fW, e1bW, e2fW, e2bW, d1fW, d1bW, d2fW, d2bW, Wd,
                         whi, wlo);

    // e1 (K=64, Nw=512, both dirs)
    hgemm2<128, 2, 4><<<dim3(4, 1024, 2), 256, GS128>>>(
        xhi, xlo, whi + O_e1f, wlo + O_e1f, whi + O_e1b, wlo + O_e1b,
        e1fb, e1bb, xz1, 64, 512, 1024, 512);
    lstm_tc<128, true><<<dim3(32, 2), 512, LS128>>>(
        xz1, (size_t)T * 1024, 1024, e1fU, e1bU, h1hi, h1lo, 256, T);

    // e2 (K=256, Nw=256)
    hgemm2<128, 2, 4><<<dim3(2, 1024, 2), 256, GS128>>>(
        h1hi, h1lo, whi + O_e2f, wlo + O_e2f, whi + O_e2b, wlo + O_e2b,
        e2fb, e2bb, xz2, 256, 256, 512, 256);
    lstm_tc<64, false><<<dim3(32, 2), 512, LS64>>>(
        xz2, (size_t)T * 512, 512, e2fU, e2bU, zhi, zlo, 128, T);

    // d1 (M=512, K=128, Nw=256)
    hgemm2<128, 2, 4><<<dim3(2, 4, 2), 256, GS128>>>(
        zhi, zlo, whi + O_d1f, wlo + O_d1f, whi + O_d1b, wlo + O_d1b,
        d1fb, d1bb, xzd1, 128, 256, 512, 256);
    lstm_tc<64, true><<<dim3(32, 2), 512, LS64>>>(
        xzd1, 512, 0, d1fU, d1bU, hd1hi, hd1lo, 128, T);

    // d2 (K=128, Nw=512)
    hgemm2<128, 2, 4><<<dim3(4, 1024, 2), 256, GS128>>>(
        hd1hi, hd1lo, whi + O_d2f, wlo + O_d2f, whi + O_d2b, wlo + O_d2b,
        d2fb, d2bb, xz1, 128, 512, 1024, 512);
    lstm_tc<128, true><<<dim3(32, 2), 512, LS128>>>(
        xz1, (size_t)T * 1024, 1024, d2fU, d2bU, h1hi, h1lo, 256, T);

    // dense (K=256, Nw=64, single dir)
    hgemm2<64, 4, 2><<<dim3(1, 1024, 1), 256, GS64>>>(
        h1hi, h1lo, whi + O_wd, wlo + O_wd, whi + O_wd, wlo + O_wd,
        bd, bd, (float*)d_out, 256, 64, 64, 0);
}

// round 14
// speedup vs baseline: 1.4494x; 1.0349x over previous
#include <cuda_runtime.h>
#include <cuda_bf16.h>
#include <cuda_fp16.h>
#include <math.h>
#include <stdint.h>

#define BT 131072
typedef unsigned long long u64;
typedef unsigned int u32;
typedef __nv_bfloat16 bf16;

// scratch (g_xz* reinterpreted as half planes)
__device__ float g_xz1 [67108864];    // as half: [BT,1024]
__device__ float g_xz2 [33554432];    // as half: [BT, 512]
__device__ float g_xzd1[131072];      // as half: [B, 512]
// bf16 hi/lo planes
__device__ bf16 g_xhi  [8388608],  g_xlo  [8388608];
__device__ bf16 g_h1hi [33554432], g_h1lo [33554432];
__device__ bf16 g_hd1hi[16777216], g_hd1lo[16777216];
__device__ bf16 g_zhi  [65536],    g_zlo  [65536];
__device__ bf16 g_whi  [409600],   g_wlo  [409600];

__device__ __forceinline__ float sigm(float x) {
    return __fdividef(1.0f, 1.0f + __expf(-x));
}
__device__ __forceinline__ u32 smem_u32(const void* p) {
    u32 a; asm("{ .reg .u64 t; cvta.to.shared.u64 t, %1; cvt.u32.u64 %0, t; }"
               : "=r"(a) : "l"(p));
    return a;
}
__device__ __forceinline__ u32 pkbf(float a, float b) {
    __nv_bfloat162 t = __floats2bfloat162_rn(a, b);
    return *reinterpret_cast<u32*>(&t);
}
__device__ __forceinline__ float bres(float x) {
    return x - __bfloat162float(__float2bfloat16_rn(x));
}
__device__ __forceinline__ u32 pkh2(float a, float b) {
    __half2 h = __floats2half2_rn(a, b);
    return *reinterpret_cast<u32*>(&h);
}
__device__ __forceinline__ u64 pkh64(float a, float b, float c, float d) {
    return (u64)pkh2(a, b) | ((u64)pkh2(c, d) << 32);
}
__device__ __forceinline__ void ldsm4(u32 &r0, u32 &r1, u32 &r2, u32 &r3, u32 a) {
    asm volatile("ldmatrix.sync.aligned.m8n8.x4.shared.b16 {%0,%1,%2,%3}, [%4];"
                 : "=r"(r0), "=r"(r1), "=r"(r2), "=r"(r3) : "r"(a));
}
__device__ __forceinline__ void ldsm4t(u32 &r0, u32 &r1, u32 &r2, u32 &r3, u32 a) {
    asm volatile("ldmatrix.sync.aligned.m8n8.x4.trans.shared.b16 {%0,%1,%2,%3}, [%4];"
                 : "=r"(r0), "=r"(r1), "=r"(r2), "=r"(r3) : "r"(a));
}
__device__ __forceinline__ void mma_bf16(float* c, const u32* a, const u32* b) {
    asm volatile("mma.sync.aligned.m16n8k16.row.col.f32.bf16.bf16.f32 "
                 "{%0,%1,%2,%3}, {%4,%5,%6,%7}, {%8,%9}, {%0,%1,%2,%3};"
                 : "+f"(c[0]), "+f"(c[1]), "+f"(c[2]), "+f"(c[3])
                 : "r"(a[0]), "r"(a[1]), "r"(a[2]), "r"(a[3]), "r"(b[0]), "r"(b[1]));
}
__device__ __forceinline__ void mma_f16(float* c, const u32* a, u32 b0, u32 b1) {
    asm volatile("mma.sync.aligned.m16n8k16.row.col.f32.f16.f16.f32 "
                 "{%0,%1,%2,%3}, {%4,%5,%6,%7}, {%8,%9}, {%0,%1,%2,%3};"
                 : "+f"(c[0]), "+f"(c[1]), "+f"(c[2]), "+f"(c[3])
                 : "r"(a[0]), "r"(a[1]), "r"(a[2]), "r"(a[3]), "r"(b0), "r"(b1));
}
__device__ __forceinline__ void cp8(u32 d, const void* s) {
    asm volatile("cp.async.ca.shared.global [%0], [%1], 8;" :: "r"(d), "l"(s));
}
__device__ __forceinline__ void cp16(u32 d, const void* s) {
    asm volatile("cp.async.ca.shared.global [%0], [%1], 16;" :: "r"(d), "l"(s));
}

// ---------------------------------------------------------------------------
// Converters (proven)
// ---------------------------------------------------------------------------
__global__ void cvt_x(const float* __restrict__ s, bf16* __restrict__ hi,
                      bf16* __restrict__ lo, int n4)
{
    for (int i = blockIdx.x * blockDim.x + threadIdx.x; i < n4;
         i += gridDim.x * blockDim.x) {
        float4 v = ((const float4*)s)[i];
        ((uint2*)hi)[i] = make_uint2(pkbf(v.x, v.y), pkbf(v.z, v.w));
        ((uint2*)lo)[i] = make_uint2(pkbf(bres(v.x), bres(v.y)),
                                     pkbf(bres(v.z), bres(v.w)));
    }
}

__global__ void cvt_w9(const float* w0, const float* w1, const float* w2,
                       const float* w3, const float* w4, const float* w5,
                       const float* w6, const float* w7, const float* w8,
                       bf16* __restrict__ hi, bf16* __restrict__ lo)
{
    const int off[10] = {0, 8192, 16384, 32768, 49152, 57344,
                         65536, 81920, 98304, 102400};
    const float* ws[9] = {w0, w1, w2, w3, w4, w5, w6, w7, w8};
    for (int i = blockIdx.x * blockDim.x + threadIdx.x; i < 102400;
         i += gridDim.x * blockDim.x) {
        int s = 0;
        #pragma unroll
        for (int k = 1; k < 9; k++) if (i >= off[k]) s = k;
        float4 v = ((const float4*)ws[s])[i - off[s]];
        ((uint2*)hi)[i] = make_uint2(pkbf(v.x, v.y), pkbf(v.z, v.w));
        ((uint2*)lo)[i] = make_uint2(pkbf(bres(v.x), bres(v.y)),
                                     pkbf(bres(v.z), bres(v.w)));
    }
}

// ---------------------------------------------------------------------------
// hgemm2 (proven), output type templated: half (xz planes) or float (dense).
// ---------------------------------------------------------------------------
template<int NT>
__device__ __forceinline__ void g2s_chunk(
    u32 sbase, const bf16* Ahi, const bf16* Alo,
    const bf16* Whi, const bf16* Wlo,
    int bm, int bn, int k0, int K, int Nw, int tid)
{
    constexpr int PA = 80, ASZ = 128 * PA;
    constexpr int PB = NT * 2 + 16, WSZ = 32 * PB;
    constexpr int WOPS = NT / 32;
    {
        int row = tid & 127;
        const bf16* src = ((tid & 128) ? Alo : Ahi) + (size_t)(bm + row) * K + k0;
        u32 dst = sbase + ((tid & 128) ? ASZ : 0) + row * PA;
        #pragma unroll
        for (int i = 0; i < 8; i++)
            cp8(dst + i * 8, (const char*)src + i * 8);
    }
    {
        int idx = tid & 127, row = idx >> 2, seg = idx & 3;
        const bf16* src = ((tid & 128) ? Wlo : Whi)
                          + (size_t)(k0 + row) * Nw + bn + seg * (NT / 4);
        u32 dst = sbase + 2 * ASZ + ((tid & 128) ? WSZ : 0) + row * PB + seg * (NT / 2);
        #pragma unroll
        for (int i = 0; i < WOPS; i++)
            cp16(dst + i * 16, (const char*)src + i * 16);
    }
}

template<int NT, int WM, int WN, typename CT>
__global__ __launch_bounds__(256, 2)
void hgemm2(const bf16* __restrict__ Ahi, const bf16* __restrict__ Alo,
            const bf16* __restrict__ Whi0, const bf16* __restrict__ Wlo0,
            const bf16* __restrict__ Whi1, const bf16* __restrict__ Wlo1,
            const float* __restrict__ bias0, const float* __restrict__ bias1,
            CT* __restrict__ C, int K, int Nw, int ldc, int coff)
{
    constexpr int PA = 80, ASZ = 128 * PA;
    constexpr int PB = NT * 2 + 16, WSZ = 32 * PB;
    constexpr int STG = 2 * ASZ + 2 * WSZ;
    constexpr int MW = 128 / WM, NWT = NT / WN;
    constexpr int MFRAG = MW / 16, NFRAG = NWT / 8;
    extern __shared__ char gsm[];

    const int tid = threadIdx.x, wid = tid >> 5, lane = tid & 31;
    const int bm = blockIdx.y * 128, bn = blockIdx.x * NT, dir = blockIdx.z;
    const int wm = (wid / WN) * MW, wn = (wid % WN) * NWT;
    const bf16* Whi = dir ? Whi1 : Whi0;
    const bf16* Wlo = dir ? Wlo1 : Wlo0;
    const float* bias = dir ? bias1 : bias0;
    const int cofs = dir * coff;
    const u32 sb = smem_u32(gsm);

    float acc[MFRAG][NFRAG][4];
    #pragma unroll
    for (int i = 0; i < MFRAG; i++)
        #pragma unroll
        for (int j = 0; j < NFRAG; j++)
            #pragma unroll
            for (int q = 0; q < 4; q++) acc[i][j][q] = 0.f;

    g2s_chunk<NT>(sb, Ahi, Alo, Whi, Wlo, bm, bn, 0, K, Nw, tid);
    asm volatile("cp.async.commit_group;" ::: "memory");

    const int nch = K / 32;
    for (int ch = 0; ch < nch; ch++) {
        asm volatile("cp.async.wait_group 0;" ::: "memory");
        __syncthreads();
        const u32 s0 = sb + (u32)(ch & 1) * STG;
        if (ch + 1 < nch) {
            g2s_chunk<NT>(sb + (u32)((ch + 1) & 1) * STG, Ahi, Alo, Whi, Wlo,
                          bm, bn, (ch + 1) * 32, K, Nw, tid);
            asm volatile("cp.async.commit_group;" ::: "memory");
        }
        const u32 saH = s0, saL = s0 + ASZ, swH = s0 + 2 * ASZ, swL = swH + WSZ;
        #pragma unroll
        for (int s = 0; s < 2; s++) {
            u32 wh[NFRAG][2], wl[NFRAG][2];
            #pragma unroll
            for (int np = 0; np < NFRAG / 2; np++) {
                u32 r0, r1, r2, r3;
                const u32 colb = 2 * (u32)(wn + np * 16 + ((lane >> 4) << 3));
                const u32 rowb = (u32)(s * 16 + (lane & 15)) * PB;
                ldsm4t(r0, r1, r2, r3, swH + rowb + colb);
                wh[2*np][0] = r0; wh[2*np][1] = r1;
                wh[2*np+1][0] = r2; wh[2*np+1][1] = r3;
                ldsm4t(r0, r1, r2, r3, swL + rowb + colb);
                wl[2*np][0] = r0; wl[2*np][1] = r1;
                wl[2*np+1][0] = r2; wl[2*np+1][1] = r3;
            }
            u32 a[MFRAG][4];
            #pragma unroll
            for (int mf = 0; mf < MFRAG; mf++)
                ldsm4(a[mf][0], a[mf][1], a[mf][2], a[mf][3],
                      saH + (u32)(wm + mf * 16 + (lane & 15)) * PA
                          + s * 32 + ((lane >> 4) << 4));
            #pragma unroll
            for (int mf = 0; mf < MFRAG; mf++)
                #pragma unroll
                for (int nf = 0; nf < NFRAG; nf++) {
                    mma_bf16(acc[mf][nf], a[mf], wh[nf]);
                    mma_bf16(acc[mf][nf], a[mf], wl[nf]);
                }
            #pragma unroll
            for (int mf = 0; mf < MFRAG; mf++)
                ldsm4(a[mf][0], a[mf][1], a[mf][2], a[mf][3],
                      saL + (u32)(wm + mf * 16 + (lane & 15)) * PA
                          + s * 32 + ((lane >> 4) << 4));
            #pragma unroll
            for (int mf = 0; mf < MFRAG; mf++)
                #pragma unroll
                for (int nf = 0; nf < NFRAG; nf++)
                    mma_bf16(acc[mf][nf], a[mf], wh[nf]);
        }
        __syncthreads();
    }

    #pragma unroll
    for (int mf = 0; mf < MFRAG; mf++) {
        #pragma unroll
        for (int nf = 0; nf < NFRAG; nf++) {
            const int r0 = bm + wm + mf * 16 + (lane >> 2);
            const int col = bn + wn + nf * 8 + (lane & 3) * 2;
            const float b0 = bias[col], b1 = bias[col + 1];
            float v00 = acc[mf][nf][0] + b0, v01 = acc[mf][nf][1] + b1;
            float v10 = acc[mf][nf][2] + b0, v11 = acc[mf][nf][3] + b1;
            if constexpr (sizeof(CT) == 2) {
                *(u32*)&C[(size_t)r0 * ldc + cofs + col]       = pkh2(v00, v01);
                *(u32*)&C[(size_t)(r0 + 8) * ldc + cofs + col] = pkh2(v10, v11);
            } else {
                *(float2*)&C[(size_t)r0 * ldc + cofs + col] = make_float2(v00, v01);
                *(float2*)&C[(size_t)(r0 + 8) * ldc + cofs + col] = make_float2(v10, v11);
            }
        }
    }
}

// ---------------------------------------------------------------------------
// Tensor-core LSTM (R13, proven) — xz now read as f16.
// ---------------------------------------------------------------------------
template<int HU, bool SEQ>
__global__ __launch_bounds__(512, 1)
void lstm_tc(const __half* __restrict__ xz, size_t strideB, size_t strideT,
             const float* __restrict__ Uf, const float* __restrict__ Ub,
             bf16* __restrict__ ohi, bf16* __restrict__ olo, int ldo, int T)
{
    constexpr int NG = 4 * HU, NW = NG / 16, NFRAG = NW / 8;
    constexpr int KF = HU / 16, NFG = NG / 8;
    constexpr int HP = HU + 8;
    constexpr int GP = NG + 4;
    constexpr int NC = HU / 32;

    extern __shared__ char sm[];
    u64*    Uhi  = (u64*)sm;                        // [KF*NFG*32]
    __half* hhi  = (__half*)(Uhi + KF * NFG * 32);  // [16*HP]
    float*  gbuf = (float*)(hhi + 16 * HP);         // [16*GP]

    const int tid = threadIdx.x, wid = tid >> 5, lane = tid & 31;
    const int g = lane >> 2, c2 = (lane & 3) * 2;
    const int dir = blockIdx.y, b0 = blockIdx.x * 16;
    const float* U    = dir ? Ub : Uf;
    const __half* xzd = xz + (size_t)dir * NG;
    bf16* ohid = ohi + dir * HU;
    bf16* olid = olo + dir * HU;

    for (int idx = tid; idx < KF * NFG * 32; idx += 512) {
        int ln = idx & 31, fr = idx >> 5;
        int nfg = fr % NFG, kf = fr / NFG;
        int n = nfg * 8 + (ln >> 2);
        int k0 = kf * 16 + 2 * (ln & 3);
        float x0 = U[(size_t)k0 * NG + n],       x1 = U[(size_t)(k0 + 1) * NG + n];
        float x2 = U[(size_t)(k0 + 8) * NG + n], x3 = U[(size_t)(k0 + 9) * NG + n];
        Uhi[idx] = pkh64(__half2float(__float2half_rn(x0)),
                         __half2float(__float2half_rn(x1)),
                         __half2float(__float2half_rn(x2)),
                         __half2float(__float2half_rn(x3)));
    }
    for (int idx = tid; idx < 16 * HP / 2; idx += 512)
        ((u32*)hhi)[idx] = 0;
    __syncthreads();

    const int gate = (wid * NW) / HU;
    const int ur = tid >> 5, uj = (tid & 31) * NC;
    float cst[NC];
    #pragma unroll
    for (int i = 0; i < NC; i++) cst[i] = 0.f;

    for (int t = 0; t < T; t++) {
        const int tt = dir ? (T - 1 - t) : t;

        float xv[NFRAG][4];
        {
            const __half* xp0 = xzd + (size_t)(b0 + g) * strideB
                                + (size_t)tt * strideT + wid * NW + c2;
            const __half* xp1 = xp0 + 8 * strideB;
            #pragma unroll
            for (int nf = 0; nf < NFRAG; nf++) {
                float2 v0 = __half22float2(*(const __half2*)(xp0 + nf * 8));
                float2 v1 = __half22float2(*(const __half2*)(xp1 + nf * 8));
                xv[nf][0] = v0.x; xv[nf][1] = v0.y;
                xv[nf][2] = v1.x; xv[nf][3] = v1.y;
            }
        }

        float acc[NFRAG][4];
        #pragma unroll
        for (int nf = 0; nf < NFRAG; nf++)
            #pragma unroll
            for (int q = 0; q < 4; q++) acc[nf][q] = 0.f;

        #pragma unroll
        for (int kf = 0; kf < KF; kf++) {
            const int kb = kf * 16 + c2;
            u32 a[4];
            a[0] = *(const u32*)&hhi[g * HP + kb];
            a[1] = *(const u32*)&hhi[(g + 8) * HP + kb];
            a[2] = *(const u32*)&hhi[g * HP + kb + 8];
            a[3] = *(const u32*)&hhi[(g + 8) * HP + kb + 8];
            const u64* ub = Uhi + ((size_t)kf * NFG + wid * NFRAG) * 32 + lane;
            #pragma unroll
            for (int nf = 0; nf < NFRAG; nf++) {
                u64 b = ub[nf * 32];
                mma_f16(acc[nf], a, (u32)b, (u32)(b >> 32));
            }
        }

        #pragma unroll
        for (int nf = 0; nf < NFRAG; nf++) {
            const int n = wid * NW + nf * 8 + c2;
            float z0 = acc[nf][0] + xv[nf][0], z1 = acc[nf][1] + xv[nf][1];
            float z2 = acc[nf][2] + xv[nf][2], z3 = acc[nf][3] + xv[nf][3];
            float2 w0, w1;
            if (gate == 2) {
                w0 = make_float2(fmaxf(z0, 0.f), fmaxf(z1, 0.f));
                w1 = make_float2(fmaxf(z2, 0.f), fmaxf(z3, 0.f));
            } else {
                w0 = make_float2(sigm(z0), sigm(z1));
                w1 = make_float2(sigm(z2), sigm(z3));
            }
            *(float2*)&gbuf[g * GP + n]       = w0;
            *(float2*)&gbuf[(g + 8) * GP + n] = w1;
        }
        __syncthreads();

        {
            float iv[NC], fv[NC], gv[NC], ov[NC], ho[NC];
            const float* gb = gbuf + ur * GP + uj;
            if constexpr (NC == 4) {
                *(float4*)iv = *(const float4*)(gb);
                *(float4*)fv = *(const float4*)(gb + HU);
                *(float4*)gv = *(const float4*)(gb + 2 * HU);
                *(float4*)ov = *(const float4*)(gb + 3 * HU);
            } else {
                *(float2*)iv = *(const float2*)(gb);
                *(float2*)fv = *(const float2*)(gb + HU);
                *(float2*)gv = *(const float2*)(gb + 2 * HU);
                *(float2*)ov = *(const float2*)(gb + 3 * HU);
            }
            #pragma unroll
            for (int i = 0; i < NC; i++) {
                cst[i] = fv[i] * cst[i] + iv[i] * gv[i];
                ho[i] = ov[i] * fmaxf(cst[i], 0.f);
            }
            if (SEQ || t == T - 1) {
                size_t idx = SEQ ? (((size_t)(b0 + ur) * T + tt) * ldo + uj)
                                 : ((size_t)(b0 + ur) * ldo + uj);
                u32 hw0 = pkbf(ho[0], ho[1]);
                u32 lw0 = pkbf(bres(ho[0]), bres(ho[1]));
                if constexpr (NC == 4) {
                    u32 hw1 = pkbf(ho[2], ho[3]);
                    u32 lw1 = pkbf(bres(ho[2]), bres(ho[3]));
                    *(uint2*)(ohid + idx) = make_uint2(hw0, hw1);
                    *(uint2*)(olid + idx) = make_uint2(lw0, lw1);
                } else {
                    *(u32*)(ohid + idx) = hw0;
                    *(u32*)(olid + idx) = lw0;
                }
            }
            u32 hw[NC / 2];
            #pragma unroll
            for (int q = 0; q < NC / 2; q++)
                hw[q] = pkh2(ho[2 * q], ho[2 * q + 1]);
            u32* hp = (u32*)&hhi[ur * HP + uj];
            if constexpr (NC == 4)
                *(uint2*)hp = make_uint2(hw[0], hw[1]);
            else
                hp[0] = hw[0];
        }
        __syncthreads();
    }
}

// ---------------------------------------------------------------------------
extern "C" void kernel_launch(void* const* d_in, const int* in_sizes, int n_in,
                              void* d_out, int out_size)
{
    const float* x    = (const float*)d_in[0];
    const float* e1fW = (const float*)d_in[1];
    const float* e1fU = (const float*)d_in[2];
    const float* e1fb = (const float*)d_in[3];
    const float* e1bW = (const float*)d_in[4];
    const float* e1bU = (const float*)d_in[5];
    const float* e1bb = (const float*)d_in[6];
    const float* e2fW = (const float*)d_in[7];
    const float* e2fU = (const float*)d_in[8];
    const float* e2fb = (const float*)d_in[9];
    const float* e2bW = (const float*)d_in[10];
    const float* e2bU = (const float*)d_in[11];
    const float* e2bb = (const float*)d_in[12];
    const float* d1fW = (const float*)d_in[13];
    const float* d1fU = (const float*)d_in[14];
    const float* d1fb = (const float*)d_in[15];
    const float* d1bW = (const float*)d_in[16];
    const float* d1bU = (const float*)d_in[17];
    const float* d1bb = (const float*)d_in[18];
    const float* d2fW = (const float*)d_in[19];
    const float* d2fU = (const float*)d_in[20];
    const float* d2fb = (const float*)d_in[21];
    const float* d2bW = (const float*)d_in[22];
    const float* d2bU = (const float*)d_in[23];
    const float* d2bb = (const float*)d_in[24];
    const float* Wd   = (const float*)d_in[25];
    const float* bd   = (const float*)d_in[26];

    float *p1, *p2, *p3;
    bf16 *xhi, *xlo, *h1hi, *h1lo, *hd1hi, *hd1lo, *zhi, *zlo, *whi, *wlo;
    cudaGetSymbolAddress((void**)&p1,    g_xz1);
    cudaGetSymbolAddress((void**)&p2,    g_xz2);
    cudaGetSymbolAddress((void**)&p3,    g_xzd1);
    cudaGetSymbolAddress((void**)&xhi,   g_xhi);
    cudaGetSymbolAddress((void**)&xlo,   g_xlo);
    cudaGetSymbolAddress((void**)&h1hi,  g_h1hi);
    cudaGetSymbolAddress((void**)&h1lo,  g_h1lo);
    cudaGetSymbolAddress((void**)&hd1hi, g_hd1hi);
    cudaGetSymbolAddress((void**)&hd1lo, g_hd1lo);
    cudaGetSymbolAddress((void**)&zhi,   g_zhi);
    cudaGetSymbolAddress((void**)&zlo,   g_zlo);
    cudaGetSymbolAddress((void**)&whi,   g_whi);
    cudaGetSymbolAddress((void**)&wlo,   g_wlo);
    __half* xz1  = (__half*)p1;
    __half* xz2  = (__half*)p2;
    __half* xzd1 = (__half*)p3;

    const int O_e1f = 0,      O_e1b = 32768,  O_e2f = 65536,  O_e2b = 131072;
    const int O_d1f = 196608, O_d1b = 229376, O_d2f = 262144, O_d2b = 327680;
    const int O_wd  = 393216;

    const int LS128 = 131072 + 16 * 136 * 2 + 16 * 516 * 4;
    const int LS64  = 32768 + 16 * 72 * 2 + 16 * 260 * 4;
    cudaFuncSetAttribute(lstm_tc<128, true>,
                         cudaFuncAttributeMaxDynamicSharedMemorySize, LS128);
    cudaFuncSetAttribute(lstm_tc<64, false>,
                         cudaFuncAttributeMaxDynamicSharedMemorySize, LS64);
    cudaFuncSetAttribute(lstm_tc<64, true>,
                         cudaFuncAttributeMaxDynamicSharedMemorySize, LS64);

    const int GS128 = 2 * (2 * 128 * 80 + 2 * 32 * 272);
    const int GS64  = 2 * (2 * 128 * 80 + 2 * 32 * 144);
    cudaFuncSetAttribute(hgemm2<128, 2, 4, __half>,
                         cudaFuncAttributeMaxDynamicSharedMemorySize, GS128);
    cudaFuncSetAttribute(hgemm2<64, 4, 2, float>,
                         cudaFuncAttributeMaxDynamicSharedMemorySize, GS64);

    const int T = 256;

    cvt_x<<<2048, 256>>>(x, xhi, xlo, 2097152);
    cvt_w9<<<256, 256>>>(e1fW, e1bW, e2fW, e2bW, d1fW, d1bW, d2fW, d2bW, Wd,
                         whi, wlo);

    // e1 (K=64, Nw=512, both dirs)
    hgemm2<128, 2, 4, __half><<<dim3(4, 1024, 2), 256, GS128>>>(
        xhi, xlo, whi + O_e1f, wlo + O_e1f, whi + O_e1b, wlo + O_e1b,
        e1fb, e1bb, xz1, 64, 512, 1024, 512);
    lstm_tc<128, true><<<dim3(32, 2), 512, LS128>>>(
        xz1, (size_t)T * 1024, 1024, e1fU, e1bU, h1hi, h1lo, 256, T);

    // e2 (K=256, Nw=256)
    hgemm2<128, 2, 4, __half><<<dim3(2, 1024, 2), 256, GS128>>>(
        h1hi, h1lo, whi + O_e2f, wlo + O_e2f, whi + O_e2b, wlo + O_e2b,
        e2fb, e2bb, xz2, 256, 256, 512, 256);
    lstm_tc<64, false><<<dim3(32, 2), 512, LS64>>>(
        xz2, (size_t)T * 512, 512, e2fU, e2bU, zhi, zlo, 128, T);

    // d1 (M=512, K=128, Nw=256)
    hgemm2<128, 2, 4, __half><<<dim3(2, 4, 2), 256, GS128>>>(
        zhi, zlo, whi + O_d1f, wlo + O_d1f, whi + O_d1b, wlo + O_d1b,
        d1fb, d1bb, xzd1, 128, 256, 512, 256);
    lstm_tc<64, true><<<dim3(32, 2), 512, LS64>>>(
        xzd1, 512, 0, d1fU, d1bU, hd1hi, hd1lo, 128, T);

    // d2 (K=128, Nw=512)
    hgemm2<128, 2, 4, __half><<<dim3(4, 1024, 2), 256, GS128>>>(
        hd1hi, hd1lo, whi + O_d2f, wlo + O_d2f, whi + O_d2b, wlo + O_d2b,
        d2fb, d2bb, xz1, 128, 512, 1024, 512);
    lstm_tc<128, true><<<dim3(32, 2), 512, LS128>>>(
        xz1, (size_t)T * 1024, 1024, d2fU, d2bU, h1hi, h1lo, 256, T);

    // dense (K=256, Nw=64, single dir, fp32 out)
    hgemm2<64, 4, 2, float><<<dim3(1, 1024, 1), 256, GS64>>>(
        h1hi, h1lo, whi + O_wd, wlo + O_wd, whi + O_wd, wlo + O_wd,
        bd, bd, (float*)d_out, 256, 64, 64, 0);
}

// round 15
// speedup vs baseline: 1.5577x; 1.0747x over previous
#include <cuda_runtime.h>
#include <cuda_bf16.h>
#include <cuda_fp16.h>
#include <math.h>
#include <stdint.h>

#define BT 131072
typedef unsigned long long u64;
typedef unsigned int u32;
typedef __nv_bfloat16 bf16;

// scratch (g_xz* reinterpreted as half planes)
__device__ float g_xz1 [67108864];    // as half: [BT,1024]
__device__ float g_xz2 [33554432];    // as half: [BT, 512]
__device__ float g_xzd1[131072];      // as half: [B, 512]
// bf16 hi/lo planes
__device__ bf16 g_xhi  [8388608],  g_xlo  [8388608];
__device__ bf16 g_h1hi [33554432], g_h1lo [33554432];
__device__ bf16 g_hd1hi[16777216], g_hd1lo[16777216];
__device__ bf16 g_zhi  [65536],    g_zlo  [65536];
__device__ bf16 g_whi  [409600],   g_wlo  [409600];

__device__ __forceinline__ float sigm(float x) {
    return __fdividef(1.0f, 1.0f + __expf(-x));
}
__device__ __forceinline__ u32 smem_u32(const void* p) {
    u32 a; asm("{ .reg .u64 t; cvta.to.shared.u64 t, %1; cvt.u32.u64 %0, t; }"
               : "=r"(a) : "l"(p));
    return a;
}
__device__ __forceinline__ u32 pkbf(float a, float b) {
    __nv_bfloat162 t = __floats2bfloat162_rn(a, b);
    return *reinterpret_cast<u32*>(&t);
}
__device__ __forceinline__ float bres(float x) {
    return x - __bfloat162float(__float2bfloat16_rn(x));
}
__device__ __forceinline__ u32 pkh2(float a, float b) {
    __half2 h = __floats2half2_rn(a, b);
    return *reinterpret_cast<u32*>(&h);
}
__device__ __forceinline__ u64 pkh64(float a, float b, float c, float d) {
    return (u64)pkh2(a, b) | ((u64)pkh2(c, d) << 32);
}
__device__ __forceinline__ void ldsm4(u32 &r0, u32 &r1, u32 &r2, u32 &r3, u32 a) {
    asm volatile("ldmatrix.sync.aligned.m8n8.x4.shared.b16 {%0,%1,%2,%3}, [%4];"
                 : "=r"(r0), "=r"(r1), "=r"(r2), "=r"(r3) : "r"(a));
}
__device__ __forceinline__ void ldsm4t(u32 &r0, u32 &r1, u32 &r2, u32 &r3, u32 a) {
    asm volatile("ldmatrix.sync.aligned.m8n8.x4.trans.shared.b16 {%0,%1,%2,%3}, [%4];"
                 : "=r"(r0), "=r"(r1), "=r"(r2), "=r"(r3) : "r"(a));
}
__device__ __forceinline__ void mma_bf16(float* c, const u32* a, const u32* b) {
    asm volatile("mma.sync.aligned.m16n8k16.row.col.f32.bf16.bf16.f32 "
                 "{%0,%1,%2,%3}, {%4,%5,%6,%7}, {%8,%9}, {%0,%1,%2,%3};"
                 : "+f"(c[0]), "+f"(c[1]), "+f"(c[2]), "+f"(c[3])
                 : "r"(a[0]), "r"(a[1]), "r"(a[2]), "r"(a[3]), "r"(b[0]), "r"(b[1]));
}
__device__ __forceinline__ void mma_f16(float* c, const u32* a, u32 b0, u32 b1) {
    asm volatile("mma.sync.aligned.m16n8k16.row.col.f32.f16.f16.f32 "
                 "{%0,%1,%2,%3}, {%4,%5,%6,%7}, {%8,%9}, {%0,%1,%2,%3};"
                 : "+f"(c[0]), "+f"(c[1]), "+f"(c[2]), "+f"(c[3])
                 : "r"(a[0]), "r"(a[1]), "r"(a[2]), "r"(a[3]), "r"(b0), "r"(b1));
}
__device__ __forceinline__ void cp8(u32 d, const void* s) {
    asm volatile("cp.async.ca.shared.global [%0], [%1], 8;" :: "r"(d), "l"(s));
}
__device__ __forceinline__ void cp16(u32 d, const void* s) {
    asm volatile("cp.async.ca.shared.global [%0], [%1], 16;" :: "r"(d), "l"(s));
}

// ---------------------------------------------------------------------------
// Converters (proven)
// ---------------------------------------------------------------------------
__global__ void cvt_x(const float* __restrict__ s, bf16* __restrict__ hi,
                      bf16* __restrict__ lo, int n4)
{
    for (int i = blockIdx.x * blockDim.x + threadIdx.x; i < n4;
         i += gridDim.x * blockDim.x) {
        float4 v = ((const float4*)s)[i];
        ((uint2*)hi)[i] = make_uint2(pkbf(v.x, v.y), pkbf(v.z, v.w));
        ((uint2*)lo)[i] = make_uint2(pkbf(bres(v.x), bres(v.y)),
                                     pkbf(bres(v.z), bres(v.w)));
    }
}

__global__ void cvt_w9(const float* w0, const float* w1, const float* w2,
                       const float* w3, const float* w4, const float* w5,
                       const float* w6, const float* w7, const float* w8,
                       bf16* __restrict__ hi, bf16* __restrict__ lo)
{
    const int off[10] = {0, 8192, 16384, 32768, 49152, 57344,
                         65536, 81920, 98304, 102400};
    const float* ws[9] = {w0, w1, w2, w3, w4, w5, w6, w7, w8};
    for (int i = blockIdx.x * blockDim.x + threadIdx.x; i < 102400;
         i += gridDim.x * blockDim.x) {
        int s = 0;
        #pragma unroll
        for (int k = 1; k < 9; k++) if (i >= off[k]) s = k;
        float4 v = ((const float4*)ws[s])[i - off[s]];
        ((uint2*)hi)[i] = make_uint2(pkbf(v.x, v.y), pkbf(v.z, v.w));
        ((uint2*)lo)[i] = make_uint2(pkbf(bres(v.x), bres(v.y)),
                                     pkbf(bres(v.z), bres(v.w)));
    }
}

// ---------------------------------------------------------------------------
// hgemm2 (proven), output type templated: half (xz planes) or float (dense).
// ---------------------------------------------------------------------------
template<int NT>
__device__ __forceinline__ void g2s_chunk(
    u32 sbase, const bf16* Ahi, const bf16* Alo,
    const bf16* Whi, const bf16* Wlo,
    int bm, int bn, int k0, int K, int Nw, int tid)
{
    constexpr int PA = 80, ASZ = 128 * PA;
    constexpr int PB = NT * 2 + 16, WSZ = 32 * PB;
    constexpr int WOPS = NT / 32;
    {
        int row = tid & 127;
        const bf16* src = ((tid & 128) ? Alo : Ahi) + (size_t)(bm + row) * K + k0;
        u32 dst = sbase + ((tid & 128) ? ASZ : 0) + row * PA;
        #pragma unroll
        for (int i = 0; i < 8; i++)
            cp8(dst + i * 8, (const char*)src + i * 8);
    }
    {
        int idx = tid & 127, row = idx >> 2, seg = idx & 3;
        const bf16* src = ((tid & 128) ? Wlo : Whi)
                          + (size_t)(k0 + row) * Nw + bn + seg * (NT / 4);
        u32 dst = sbase + 2 * ASZ + ((tid & 128) ? WSZ : 0) + row * PB + seg * (NT / 2);
        #pragma unroll
        for (int i = 0; i < WOPS; i++)
            cp16(dst + i * 16, (const char*)src + i * 16);
    }
}

template<int NT, int WM, int WN, typename CT>
__global__ __launch_bounds__(256, 2)
void hgemm2(const bf16* __restrict__ Ahi, const bf16* __restrict__ Alo,
            const bf16* __restrict__ Whi0, const bf16* __restrict__ Wlo0,
            const bf16* __restrict__ Whi1, const bf16* __restrict__ Wlo1,
            const float* __restrict__ bias0, const float* __restrict__ bias1,
            CT* __restrict__ C, int K, int Nw, int ldc, int coff)
{
    constexpr int PA = 80, ASZ = 128 * PA;
    constexpr int PB = NT * 2 + 16, WSZ = 32 * PB;
    constexpr int STG = 2 * ASZ + 2 * WSZ;
    constexpr int MW = 128 / WM, NWT = NT / WN;
    constexpr int MFRAG = MW / 16, NFRAG = NWT / 8;
    extern __shared__ char gsm[];

    const int tid = threadIdx.x, wid = tid >> 5, lane = tid & 31;
    const int bm = blockIdx.y * 128, bn = blockIdx.x * NT, dir = blockIdx.z;
    const int wm = (wid / WN) * MW, wn = (wid % WN) * NWT;
    const bf16* Whi = dir ? Whi1 : Whi0;
    const bf16* Wlo = dir ? Wlo1 : Wlo0;
    const float* bias = dir ? bias1 : bias0;
    const int cofs = dir * coff;
    const u32 sb = smem_u32(gsm);

    float acc[MFRAG][NFRAG][4];
    #pragma unroll
    for (int i = 0; i < MFRAG; i++)
        #pragma unroll
        for (int j = 0; j < NFRAG; j++)
            #pragma unroll
            for (int q = 0; q < 4; q++) acc[i][j][q] = 0.f;

    g2s_chunk<NT>(sb, Ahi, Alo, Whi, Wlo, bm, bn, 0, K, Nw, tid);
    asm volatile("cp.async.commit_group;" ::: "memory");

    const int nch = K / 32;
    for (int ch = 0; ch < nch; ch++) {
        asm volatile("cp.async.wait_group 0;" ::: "memory");
        __syncthreads();
        const u32 s0 = sb + (u32)(ch & 1) * STG;
        if (ch + 1 < nch) {
            g2s_chunk<NT>(sb + (u32)((ch + 1) & 1) * STG, Ahi, Alo, Whi, Wlo,
                          bm, bn, (ch + 1) * 32, K, Nw, tid);
            asm volatile("cp.async.commit_group;" ::: "memory");
        }
        const u32 saH = s0, saL = s0 + ASZ, swH = s0 + 2 * ASZ, swL = swH + WSZ;
        #pragma unroll
        for (int s = 0; s < 2; s++) {
            u32 wh[NFRAG][2], wl[NFRAG][2];
            #pragma unroll
            for (int np = 0; np < NFRAG / 2; np++) {
                u32 r0, r1, r2, r3;
                const u32 colb = 2 * (u32)(wn + np * 16 + ((lane >> 4) << 3));
                const u32 rowb = (u32)(s * 16 + (lane & 15)) * PB;
                ldsm4t(r0, r1, r2, r3, swH + rowb + colb);
                wh[2*np][0] = r0; wh[2*np][1] = r1;
                wh[2*np+1][0] = r2; wh[2*np+1][1] = r3;
                ldsm4t(r0, r1, r2, r3, swL + rowb + colb);
                wl[2*np][0] = r0; wl[2*np][1] = r1;
                wl[2*np+1][0] = r2; wl[2*np+1][1] = r3;
            }
            u32 a[MFRAG][4];
            #pragma unroll
            for (int mf = 0; mf < MFRAG; mf++)
                ldsm4(a[mf][0], a[mf][1], a[mf][2], a[mf][3],
                      saH + (u32)(wm + mf * 16 + (lane & 15)) * PA
                          + s * 32 + ((lane >> 4) << 4));
            #pragma unroll
            for (int mf = 0; mf < MFRAG; mf++)
                #pragma unroll
                for (int nf = 0; nf < NFRAG; nf++) {
                    mma_bf16(acc[mf][nf], a[mf], wh[nf]);
                    mma_bf16(acc[mf][nf], a[mf], wl[nf]);
                }
            #pragma unroll
            for (int mf = 0; mf < MFRAG; mf++)
                ldsm4(a[mf][0], a[mf][1], a[mf][2], a[mf][3],
                      saL + (u32)(wm + mf * 16 + (lane & 15)) * PA
                          + s * 32 + ((lane >> 4) << 4));
            #pragma unroll
            for (int mf = 0; mf < MFRAG; mf++)
                #pragma unroll
                for (int nf = 0; nf < NFRAG; nf++)
                    mma_bf16(acc[mf][nf], a[mf], wh[nf]);
        }
        __syncthreads();
    }

    #pragma unroll
    for (int mf = 0; mf < MFRAG; mf++) {
        #pragma unroll
        for (int nf = 0; nf < NFRAG; nf++) {
            const int r0 = bm + wm + mf * 16 + (lane >> 2);
            const int col = bn + wn + nf * 8 + (lane & 3) * 2;
            const float b0 = bias[col], b1 = bias[col + 1];
            float v00 = acc[mf][nf][0] + b0, v01 = acc[mf][nf][1] + b1;
            float v10 = acc[mf][nf][2] + b0, v11 = acc[mf][nf][3] + b1;
            if constexpr (sizeof(CT) == 2) {
                *(u32*)&C[(size_t)r0 * ldc + cofs + col]       = pkh2(v00, v01);
                *(u32*)&C[(size_t)(r0 + 8) * ldc + cofs + col] = pkh2(v10, v11);
            } else {
                *(float2*)&C[(size_t)r0 * ldc + cofs + col] = make_float2(v00, v01);
                *(float2*)&C[(size_t)(r0 + 8) * ldc + cofs + col] = make_float2(v10, v11);
            }
        }
    }
}

// ---------------------------------------------------------------------------
// Tensor-core LSTM v4: U fragments in REGISTERS (loop-invariant; each B-frag
// word consumed by exactly one warp). Zero in-loop U smem traffic.
// ---------------------------------------------------------------------------
template<int HU, bool SEQ>
__global__ __launch_bounds__(512, 1)
void lstm_tc(const __half* __restrict__ xz, size_t strideB, size_t strideT,
             const float* __restrict__ Uf, const float* __restrict__ Ub,
             bf16* __restrict__ ohi, bf16* __restrict__ olo, int ldo, int T)
{
    constexpr int NG = 4 * HU, NW = NG / 16, NFRAG = NW / 8;
    constexpr int KF = HU / 16;
    constexpr int HP = HU + 8;
    constexpr int GP = NG + 4;
    constexpr int NC = HU / 32;

    extern __shared__ char sm[];
    __half* hhi  = (__half*)sm;                     // [16*HP]
    float*  gbuf = (float*)(hhi + 16 * HP);         // [16*GP]

    const int tid = threadIdx.x, wid = tid >> 5, lane = tid & 31;
    const int g = lane >> 2, c2 = (lane & 3) * 2;
    const int dir = blockIdx.y, b0 = blockIdx.x * 16;
    const float* U    = dir ? Ub : Uf;
    const __half* xzd = xz + (size_t)dir * NG;
    bf16* ohid = ohi + dir * HU;
    bf16* olid = olo + dir * HU;

    // U fragments -> registers (one-time; this thread's lane of each frag)
    u64 ureg[KF * NFRAG];
    #pragma unroll
    for (int kf = 0; kf < KF; kf++)
        #pragma unroll
        for (int nf = 0; nf < NFRAG; nf++) {
            const int n  = (wid * NFRAG + nf) * 8 + (lane >> 2);
            const int k0 = kf * 16 + 2 * (lane & 3);
            float x0 = U[(size_t)k0 * NG + n];
            float x1 = U[(size_t)(k0 + 1) * NG + n];
            float x2 = U[(size_t)(k0 + 8) * NG + n];
            float x3 = U[(size_t)(k0 + 9) * NG + n];
            ureg[kf * NFRAG + nf] =
                pkh64(__half2float(__float2half_rn(x0)),
                      __half2float(__float2half_rn(x1)),
                      __half2float(__float2half_rn(x2)),
                      __half2float(__float2half_rn(x3)));
        }

    for (int idx = tid; idx < 16 * HP / 2; idx += 512)
        ((u32*)hhi)[idx] = 0;
    __syncthreads();

    const int gate = (wid * NW) / HU;
    const int ur = tid >> 5, uj = (tid & 31) * NC;
    float cst[NC];
    #pragma unroll
    for (int i = 0; i < NC; i++) cst[i] = 0.f;

    for (int t = 0; t < T; t++) {
        const int tt = dir ? (T - 1 - t) : t;

        // xz kept packed (half2) until epilogue — 8 regs not 16
        u32 xvp[NFRAG][2];
        {
            const __half* xp0 = xzd + (size_t)(b0 + g) * strideB
                                + (size_t)tt * strideT + wid * NW + c2;
            const __half* xp1 = xp0 + 8 * strideB;
            #pragma unroll
            for (int nf = 0; nf < NFRAG; nf++) {
                xvp[nf][0] = *(const u32*)(xp0 + nf * 8);
                xvp[nf][1] = *(const u32*)(xp1 + nf * 8);
            }
        }

        float acc[NFRAG][4];
        #pragma unroll
        for (int nf = 0; nf < NFRAG; nf++)
            #pragma unroll
            for (int q = 0; q < 4; q++) acc[nf][q] = 0.f;

        #pragma unroll
        for (int kf = 0; kf < KF; kf++) {
            const int kb = kf * 16 + c2;
            u32 a[4];
            a[0] = *(const u32*)&hhi[g * HP + kb];
            a[1] = *(const u32*)&hhi[(g + 8) * HP + kb];
            a[2] = *(const u32*)&hhi[g * HP + kb + 8];
            a[3] = *(const u32*)&hhi[(g + 8) * HP + kb + 8];
            #pragma unroll
            for (int nf = 0; nf < NFRAG; nf++) {
                u64 b = ureg[kf * NFRAG + nf];
                mma_f16(acc[nf], a, (u32)b, (u32)(b >> 32));
            }
        }

        #pragma unroll
        for (int nf = 0; nf < NFRAG; nf++) {
            const int n = wid * NW + nf * 8 + c2;
            float2 x0 = __half22float2(*(const __half2*)&xvp[nf][0]);
            float2 x1 = __half22float2(*(const __half2*)&xvp[nf][1]);
            float z0 = acc[nf][0] + x0.x, z1 = acc[nf][1] + x0.y;
            float z2 = acc[nf][2] + x1.x, z3 = acc[nf][3] + x1.y;
            float2 w0, w1;
            if (gate == 2) {
                w0 = make_float2(fmaxf(z0, 0.f), fmaxf(z1, 0.f));
                w1 = make_float2(fmaxf(z2, 0.f), fmaxf(z3, 0.f));
            } else {
                w0 = make_float2(sigm(z0), sigm(z1));
                w1 = make_float2(sigm(z2), sigm(z3));
            }
            *(float2*)&gbuf[g * GP + n]       = w0;
            *(float2*)&gbuf[(g + 8) * GP + n] = w1;
        }
        __syncthreads();

        {
            float iv[NC], fv[NC], gv[NC], ov[NC], ho[NC];
            const float* gb = gbuf + ur * GP + uj;
            if constexpr (NC == 4) {
                *(float4*)iv = *(const float4*)(gb);
                *(float4*)fv = *(const float4*)(gb + HU);
                *(float4*)gv = *(const float4*)(gb + 2 * HU);
                *(float4*)ov = *(const float4*)(gb + 3 * HU);
            } else {
                *(float2*)iv = *(const float2*)(gb);
                *(float2*)fv = *(const float2*)(gb + HU);
                *(float2*)gv = *(const float2*)(gb + 2 * HU);
                *(float2*)ov = *(const float2*)(gb + 3 * HU);
            }
            #pragma unroll
            for (int i = 0; i < NC; i++) {
                cst[i] = fv[i] * cst[i] + iv[i] * gv[i];
                ho[i] = ov[i] * fmaxf(cst[i], 0.f);
            }
            if (SEQ || t == T - 1) {
                size_t idx = SEQ ? (((size_t)(b0 + ur) * T + tt) * ldo + uj)
                                 : ((size_t)(b0 + ur) * ldo + uj);
                u32 hw0 = pkbf(ho[0], ho[1]);
                u32 lw0 = pkbf(bres(ho[0]), bres(ho[1]));
                if constexpr (NC == 4) {
                    u32 hw1 = pkbf(ho[2], ho[3]);
                    u32 lw1 = pkbf(bres(ho[2]), bres(ho[3]));
                    *(uint2*)(ohid + idx) = make_uint2(hw0, hw1);
                    *(uint2*)(olid + idx) = make_uint2(lw0, lw1);
                } else {
                    *(u32*)(ohid + idx) = hw0;
                    *(u32*)(olid + idx) = lw0;
                }
            }
            u32 hw[NC / 2];
            #pragma unroll
            for (int q = 0; q < NC / 2; q++)
                hw[q] = pkh2(ho[2 * q], ho[2 * q + 1]);
            u32* hp = (u32*)&hhi[ur * HP + uj];
            if constexpr (NC == 4)
                *(uint2*)hp = make_uint2(hw[0], hw[1]);
            else
                hp[0] = hw[0];
        }
        __syncthreads();
    }
}

// ---------------------------------------------------------------------------
extern "C" void kernel_launch(void* const* d_in, const int* in_sizes, int n_in,
                              void* d_out, int out_size)
{
    const float* x    = (const float*)d_in[0];
    const float* e1fW = (const float*)d_in[1];
    const float* e1fU = (const float*)d_in[2];
    const float* e1fb = (const float*)d_in[3];
    const float* e1bW = (const float*)d_in[4];
    const float* e1bU = (const float*)d_in[5];
    const float* e1bb = (const float*)d_in[6];
    const float* e2fW = (const float*)d_in[7];
    const float* e2fU = (const float*)d_in[8];
    const float* e2fb = (const float*)d_in[9];
    const float* e2bW = (const float*)d_in[10];
    const float* e2bU = (const float*)d_in[11];
    const float* e2bb = (const float*)d_in[12];
    const float* d1fW = (const float*)d_in[13];
    const float* d1fU = (const float*)d_in[14];
    const float* d1fb = (const float*)d_in[15];
    const float* d1bW = (const float*)d_in[16];
    const float* d1bU = (const float*)d_in[17];
    const float* d1bb = (const float*)d_in[18];
    const float* d2fW = (const float*)d_in[19];
    const float* d2fU = (const float*)d_in[20];
    const float* d2fb = (const float*)d_in[21];
    const float* d2bW = (const float*)d_in[22];
    const float* d2bU = (const float*)d_in[23];
    const float* d2bb = (const float*)d_in[24];
    const float* Wd   = (const float*)d_in[25];
    const float* bd   = (const float*)d_in[26];

    float *p1, *p2, *p3;
    bf16 *xhi, *xlo, *h1hi, *h1lo, *hd1hi, *hd1lo, *zhi, *zlo, *whi, *wlo;
    cudaGetSymbolAddress((void**)&p1,    g_xz1);
    cudaGetSymbolAddress((void**)&p2,    g_xz2);
    cudaGetSymbolAddress((void**)&p3,    g_xzd1);
    cudaGetSymbolAddress((void**)&xhi,   g_xhi);
    cudaGetSymbolAddress((void**)&xlo,   g_xlo);
    cudaGetSymbolAddress((void**)&h1hi,  g_h1hi);
    cudaGetSymbolAddress((void**)&h1lo,  g_h1lo);
    cudaGetSymbolAddress((void**)&hd1hi, g_hd1hi);
    cudaGetSymbolAddress((void**)&hd1lo, g_hd1lo);
    cudaGetSymbolAddress((void**)&zhi,   g_zhi);
    cudaGetSymbolAddress((void**)&zlo,   g_zlo);
    cudaGetSymbolAddress((void**)&whi,   g_whi);
    cudaGetSymbolAddress((void**)&wlo,   g_wlo);
    __half* xz1  = (__half*)p1;
    __half* xz2  = (__half*)p2;
    __half* xzd1 = (__half*)p3;

    const int O_e1f = 0,      O_e1b = 32768,  O_e2f = 65536,  O_e2b = 131072;
    const int O_d1f = 196608, O_d1b = 229376, O_d2f = 262144, O_d2b = 327680;
    const int O_wd  = 393216;

    // lstm smem: HU=128: 16*136*2 + 16*516*4 = 37376
    //            HU=64 : 16*72*2  + 16*260*4 = 18944
    const int LS128 = 16 * 136 * 2 + 16 * 516 * 4;
    const int LS64  = 16 * 72 * 2 + 16 * 260 * 4;
    cudaFuncSetAttribute(lstm_tc<128, true>,
                         cudaFuncAttributeMaxDynamicSharedMemorySize, LS128);
    cudaFuncSetAttribute(lstm_tc<64, false>,
                         cudaFuncAttributeMaxDynamicSharedMemorySize, LS64);
    cudaFuncSetAttribute(lstm_tc<64, true>,
                         cudaFuncAttributeMaxDynamicSharedMemorySize, LS64);

    const int GS128 = 2 * (2 * 128 * 80 + 2 * 32 * 272);
    const int GS64  = 2 * (2 * 128 * 80 + 2 * 32 * 144);
    cudaFuncSetAttribute(hgemm2<128, 2, 4, __half>,
                         cudaFuncAttributeMaxDynamicSharedMemorySize, GS128);
    cudaFuncSetAttribute(hgemm2<64, 4, 2, float>,
                         cudaFuncAttributeMaxDynamicSharedMemorySize, GS64);

    const int T = 256;

    cvt_x<<<2048, 256>>>(x, xhi, xlo, 2097152);
    cvt_w9<<<256, 256>>>(e1fW, e1bW, e2fW, e2bW, d1fW, d1bW, d2fW, d2bW, Wd,
                         whi, wlo);

    // e1 (K=64, Nw=512, both dirs)
    hgemm2<128, 2, 4, __half><<<dim3(4, 1024, 2), 256, GS128>>>(
        xhi, xlo, whi + O_e1f, wlo + O_e1f, whi + O_e1b, wlo + O_e1b,
        e1fb, e1bb, xz1, 64, 512, 1024, 512);
    lstm_tc<128, true><<<dim3(32, 2), 512, LS128>>>(
        xz1, (size_t)T * 1024, 1024, e1fU, e1bU, h1hi, h1lo, 256, T);

    // e2 (K=256, Nw=256)
    hgemm2<128, 2, 4, __half><<<dim3(2, 1024, 2), 256, GS128>>>(
        h1hi, h1lo, whi + O_e2f, wlo + O_e2f, whi + O_e2b, wlo + O_e2b,
        e2fb, e2bb, xz2, 256, 256, 512, 256);
    lstm_tc<64, false><<<dim3(32, 2), 512, LS64>>>(
        xz2, (size_t)T * 512, 512, e2fU, e2bU, zhi, zlo, 128, T);

    // d1 (M=512, K=128, Nw=256)
    hgemm2<128, 2, 4, __half><<<dim3(2, 4, 2), 256, GS128>>>(
        zhi, zlo, whi + O_d1f, wlo + O_d1f, whi + O_d1b, wlo + O_d1b,
        d1fb, d1bb, xzd1, 128, 256, 512, 256);
    lstm_tc<64, true><<<dim3(32, 2), 512, LS64>>>(
        xzd1, 512, 0, d1fU, d1bU, hd1hi, hd1lo, 128, T);

    // d2 (K=128, Nw=512)
    hgemm2<128, 2, 4, __half><<<dim3(4, 1024, 2), 256, GS128>>>(
        hd1hi, hd1lo, whi + O_d2f, wlo + O_d2f, whi + O_d2b, wlo + O_d2b,
        d2fb, d2bb, xz1, 128, 512, 1024, 512);
    lstm_tc<128, true><<<dim3(32, 2), 512, LS128>>>(
        xz1, (size_t)T * 1024, 1024, d2fU, d2bU, h1hi, h1lo, 256, T);

    // dense (K=256, Nw=64, single dir, fp32 out)
    hgemm2<64, 4, 2, float><<<dim3(1, 1024, 1), 256, GS64>>>(
        h1hi, h1lo, whi + O_wd, wlo + O_wd, whi + O_wd, wlo + O_wd,
        bd, bd, (float*)d_out, 256, 64, 64, 0);
}

// round 16
// speedup vs baseline: 1.8274x; 1.1731x over previous
#include <cuda_runtime.h>
#include <cuda_bf16.h>
#include <cuda_fp16.h>
#include <math.h>
#include <stdint.h>

#define BT 131072
typedef unsigned long long u64;
typedef unsigned int u32;
typedef __nv_bfloat16 bf16;

// scratch (g_xz* reinterpreted as half planes)
__device__ float g_xz1 [67108864];    // as half: [BT,1024]
__device__ float g_xz2 [33554432];    // as half: [BT, 512]
__device__ float g_xzd1[131072];      // as half: [B, 512]
// operand planes
__device__ bf16 g_xf   [8388608];     // x   f16 [BT,64]   (as __half)
__device__ bf16 g_h1hi [33554432], g_h1lo [33554432];   // h1 bf16 hi/lo
__device__ bf16 g_hd1f [16777216];    // hd1 f16 [BT,128]  (as __half)
__device__ bf16 g_zhi  [65536],    g_zlo  [65536];      // z bf16 hi/lo
__device__ bf16 g_whi  [409600],   g_wlo  [409600];     // bf16 weight planes
__device__ __half g_wf [196608];      // f16 weights: e1f,e1b,d2f,d2b

__device__ __forceinline__ float sigm(float x) {
    return __fdividef(1.0f, 1.0f + __expf(-x));
}
__device__ __forceinline__ u32 smem_u32(const void* p) {
    u32 a; asm("{ .reg .u64 t; cvta.to.shared.u64 t, %1; cvt.u32.u64 %0, t; }"
               : "=r"(a) : "l"(p));
    return a;
}
__device__ __forceinline__ u32 pkbf(float a, float b) {
    __nv_bfloat162 t = __floats2bfloat162_rn(a, b);
    return *reinterpret_cast<u32*>(&t);
}
__device__ __forceinline__ float bres(float x) {
    return x - __bfloat162float(__float2bfloat16_rn(x));
}
__device__ __forceinline__ u32 pkh2(float a, float b) {
    __half2 h = __floats2half2_rn(a, b);
    return *reinterpret_cast<u32*>(&h);
}
__device__ __forceinline__ u64 pkh64(float a, float b, float c, float d) {
    return (u64)pkh2(a, b) | ((u64)pkh2(c, d) << 32);
}
__device__ __forceinline__ void ldsm4(u32 &r0, u32 &r1, u32 &r2, u32 &r3, u32 a) {
    asm volatile("ldmatrix.sync.aligned.m8n8.x4.shared.b16 {%0,%1,%2,%3}, [%4];"
                 : "=r"(r0), "=r"(r1), "=r"(r2), "=r"(r3) : "r"(a));
}
__device__ __forceinline__ void ldsm4t(u32 &r0, u32 &r1, u32 &r2, u32 &r3, u32 a) {
    asm volatile("ldmatrix.sync.aligned.m8n8.x4.trans.shared.b16 {%0,%1,%2,%3}, [%4];"
                 : "=r"(r0), "=r"(r1), "=r"(r2), "=r"(r3) : "r"(a));
}
__device__ __forceinline__ void mma_bf16(float* c, const u32* a, const u32* b) {
    asm volatile("mma.sync.aligned.m16n8k16.row.col.f32.bf16.bf16.f32 "
                 "{%0,%1,%2,%3}, {%4,%5,%6,%7}, {%8,%9}, {%0,%1,%2,%3};"
                 : "+f"(c[0]), "+f"(c[1]), "+f"(c[2]), "+f"(c[3])
                 : "r"(a[0]), "r"(a[1]), "r"(a[2]), "r"(a[3]), "r"(b[0]), "r"(b[1]));
}
__device__ __forceinline__ void mma_f16(float* c, const u32* a, u32 b0, u32 b1) {
    asm volatile("mma.sync.aligned.m16n8k16.row.col.f32.f16.f16.f32 "
                 "{%0,%1,%2,%3}, {%4,%5,%6,%7}, {%8,%9}, {%0,%1,%2,%3};"
                 : "+f"(c[0]), "+f"(c[1]), "+f"(c[2]), "+f"(c[3])
                 : "r"(a[0]), "r"(a[1]), "r"(a[2]), "r"(a[3]), "r"(b0), "r"(b1));
}
__device__ __forceinline__ void cp16(u32 d, const void* s) {
    asm volatile("cp.async.ca.shared.global [%0], [%1], 16;" :: "r"(d), "l"(s));
}
__device__ __forceinline__ void cp8(u32 d, const void* s) {
    asm volatile("cp.async.ca.shared.global [%0], [%1], 8;" :: "r"(d), "l"(s));
}

// ---------------------------------------------------------------------------
// Converters
// ---------------------------------------------------------------------------
__global__ void cvt_x16(const float* __restrict__ s, __half* __restrict__ o, int n4)
{
    for (int i = blockIdx.x * blockDim.x + threadIdx.x; i < n4;
         i += gridDim.x * blockDim.x) {
        float4 v = ((const float4*)s)[i];
        ((uint2*)o)[i] = make_uint2(pkh2(v.x, v.y), pkh2(v.z, v.w));
    }
}

__global__ void cvt_wf(const float* w0, const float* w1, const float* w2,
                       const float* w3, __half* __restrict__ o)
{
    const int off[5] = {0, 8192, 16384, 32768, 49152};   // float4 units
    const float* ws[4] = {w0, w1, w2, w3};
    for (int i = blockIdx.x * blockDim.x + threadIdx.x; i < 49152;
         i += gridDim.x * blockDim.x) {
        int s = 0;
        #pragma unroll
        for (int k = 1; k < 4; k++) if (i >= off[k]) s = k;
        float4 v = ((const float4*)ws[s])[i - off[s]];
        ((uint2*)o)[i] = make_uint2(pkh2(v.x, v.y), pkh2(v.z, v.w));
    }
}

__global__ void cvt_w9(const float* w0, const float* w1, const float* w2,
                       const float* w3, const float* w4, const float* w5,
                       const float* w6, const float* w7, const float* w8,
                       bf16* __restrict__ hi, bf16* __restrict__ lo)
{
    const int off[10] = {0, 8192, 16384, 32768, 49152, 57344,
                         65536, 81920, 98304, 102400};
    const float* ws[9] = {w0, w1, w2, w3, w4, w5, w6, w7, w8};
    for (int i = blockIdx.x * blockDim.x + threadIdx.x; i < 102400;
         i += gridDim.x * blockDim.x) {
        int s = 0;
        #pragma unroll
        for (int k = 1; k < 9; k++) if (i >= off[k]) s = k;
        float4 v = ((const float4*)ws[s])[i - off[s]];
        ((uint2*)hi)[i] = make_uint2(pkbf(v.x, v.y), pkbf(v.z, v.w));
        ((uint2*)lo)[i] = make_uint2(pkbf(bres(v.x), bres(v.y)),
                                     pkbf(bres(v.z), bres(v.w)));
    }
}

// ---------------------------------------------------------------------------
// hgemm1: single-term f16 GEMM. C = A(f16) @ W(f16) + bias -> half.
// Chunk K=32, double-buffered cp.async.
// ---------------------------------------------------------------------------
template<int NT, int WM, int WN>
__global__ __launch_bounds__(256, 2)
void hgemm1(const __half* __restrict__ A,
            const __half* __restrict__ W0, const __half* __restrict__ W1,
            const float* __restrict__ bias0, const float* __restrict__ bias1,
            __half* __restrict__ C, int K, int Nw, int ldc, int coff)
{
    constexpr int PA = 80, ASZ = 128 * PA;
    constexpr int PB = NT * 2 + 16, WSZ = 32 * PB;
    constexpr int STG = ASZ + WSZ;
    constexpr int MW = 128 / WM, NWT = NT / WN;
    constexpr int MFRAG = MW / 16, NFRAG = NWT / 8;
    extern __shared__ char gsm[];

    const int tid = threadIdx.x, wid = tid >> 5, lane = tid & 31;
    const int bm = blockIdx.y * 128, bn = blockIdx.x * NT, dir = blockIdx.z;
    const int wm = (wid / WN) * MW, wn = (wid % WN) * NWT;
    const __half* W = dir ? W1 : W0;
    const float* bias = dir ? bias1 : bias0;
    const int cofs = dir * coff;
    const u32 sb = smem_u32(gsm);

    float acc[MFRAG][NFRAG][4];
    #pragma unroll
    for (int i = 0; i < MFRAG; i++)
        #pragma unroll
        for (int j = 0; j < NFRAG; j++)
            #pragma unroll
            for (int q = 0; q < 4; q++) acc[i][j][q] = 0.f;

    // loader mapping
    const int ar = tid >> 1, ah = (tid & 1);            // A: row, 32B half
    const int wr = tid >> 3, wsg = (tid & 7);           // W: row, 32B seg

    auto g2s = [&](u32 base, int k0) {
        const __half* as = A + (size_t)(bm + ar) * K + k0 + ah * 16;
        u32 ad = base + ar * PA + ah * 32;
        cp16(ad, as);
        cp16(ad + 16, as + 8);
        const __half* wsrc = W + (size_t)(k0 + wr) * Nw + bn + wsg * 16;
        u32 wd = base + ASZ + wr * PB + wsg * 32;
        cp16(wd, wsrc);
        cp16(wd + 16, wsrc + 8);
    };

    g2s(sb, 0);
    asm volatile("cp.async.commit_group;" ::: "memory");

    const int nch = K / 32;
    for (int ch = 0; ch < nch; ch++) {
        asm volatile("cp.async.wait_group 0;" ::: "memory");
        __syncthreads();
        const u32 s0 = sb + (u32)(ch & 1) * STG;
        if (ch + 1 < nch) {
            g2s(sb + (u32)((ch + 1) & 1) * STG, (ch + 1) * 32);
            asm volatile("cp.async.commit_group;" ::: "memory");
        }
        const u32 sa = s0, sw = s0 + ASZ;
        #pragma unroll
        for (int s = 0; s < 2; s++) {
            u32 wf[NFRAG][2];
            #pragma unroll
            for (int np = 0; np < NFRAG / 2; np++) {
                u32 r0, r1, r2, r3;
                ldsm4t(r0, r1, r2, r3,
                       sw + (u32)(s * 16 + (lane & 15)) * PB
                          + 2 * (u32)(wn + np * 16 + ((lane >> 4) << 3)));
                wf[2*np][0] = r0; wf[2*np][1] = r1;
                wf[2*np+1][0] = r2; wf[2*np+1][1] = r3;
            }
            u32 a[MFRAG][4];
            #pragma unroll
            for (int mf = 0; mf < MFRAG; mf++)
                ldsm4(a[mf][0], a[mf][1], a[mf][2], a[mf][3],
                      sa + (u32)(wm + mf * 16 + (lane & 15)) * PA
                         + s * 32 + ((lane >> 4) << 4));
            #pragma unroll
            for (int mf = 0; mf < MFRAG; mf++)
                #pragma unroll
                for (int nf = 0; nf < NFRAG; nf++)
                    mma_f16(acc[mf][nf], a[mf], wf[nf][0], wf[nf][1]);
        }
        __syncthreads();
    }

    #pragma unroll
    for (int mf = 0; mf < MFRAG; mf++) {
        #pragma unroll
        for (int nf = 0; nf < NFRAG; nf++) {
            const int r0 = bm + wm + mf * 16 + (lane >> 2);
            const int col = bn + wn + nf * 8 + (lane & 3) * 2;
            const float b0 = bias[col], b1 = bias[col + 1];
            *(u32*)&C[(size_t)r0 * ldc + cofs + col] =
                pkh2(acc[mf][nf][0] + b0, acc[mf][nf][1] + b1);
            *(u32*)&C[(size_t)(r0 + 8) * ldc + cofs + col] =
                pkh2(acc[mf][nf][2] + b0, acc[mf][nf][3] + b1);
        }
    }
}

// ---------------------------------------------------------------------------
// hgemm2 (proven 3-term bf16), CT = half or float output.
// ---------------------------------------------------------------------------
template<int NT>
__device__ __forceinline__ void g2s_chunk(
    u32 sbase, const bf16* Ahi, const bf16* Alo,
    const bf16* Whi, const bf16* Wlo,
    int bm, int bn, int k0, int K, int Nw, int tid)
{
    constexpr int PA = 80, ASZ = 128 * PA;
    constexpr int PB = NT * 2 + 16, WSZ = 32 * PB;
    constexpr int WOPS = NT / 32;
    {
        int row = tid & 127;
        const bf16* src = ((tid & 128) ? Alo : Ahi) + (size_t)(bm + row) * K + k0;
        u32 dst = sbase + ((tid & 128) ? ASZ : 0) + row * PA;
        #pragma unroll
        for (int i = 0; i < 8; i++)
            cp8(dst + i * 8, (const char*)src + i * 8);
    }
    {
        int idx = tid & 127, row = idx >> 2, seg = idx & 3;
        const bf16* src = ((tid & 128) ? Wlo : Whi)
                          + (size_t)(k0 + row) * Nw + bn + seg * (NT / 4);
        u32 dst = sbase + 2 * ASZ + ((tid & 128) ? WSZ : 0) + row * PB + seg * (NT / 2);
        #pragma unroll
        for (int i = 0; i < WOPS; i++)
            cp16(dst + i * 16, (const char*)src + i * 16);
    }
}

template<int NT, int WM, int WN, typename CT>
__global__ __launch_bounds__(256, 2)
void hgemm2(const bf16* __restrict__ Ahi, const bf16* __restrict__ Alo,
            const bf16* __restrict__ Whi0, const bf16* __restrict__ Wlo0,
            const bf16* __restrict__ Whi1, const bf16* __restrict__ Wlo1,
            const float* __restrict__ bias0, const float* __restrict__ bias1,
            CT* __restrict__ C, int K, int Nw, int ldc, int coff)
{
    constexpr int PA = 80, ASZ = 128 * PA;
    constexpr int PB = NT * 2 + 16, WSZ = 32 * PB;
    constexpr int STG = 2 * ASZ + 2 * WSZ;
    constexpr int MW = 128 / WM, NWT = NT / WN;
    constexpr int MFRAG = MW / 16, NFRAG = NWT / 8;
    extern __shared__ char gsm[];

    const int tid = threadIdx.x, wid = tid >> 5, lane = tid & 31;
    const int bm = blockIdx.y * 128, bn = blockIdx.x * NT, dir = blockIdx.z;
    const int wm = (wid / WN) * MW, wn = (wid % WN) * NWT;
    const bf16* Whi = dir ? Whi1 : Whi0;
    const bf16* Wlo = dir ? Wlo1 : Wlo0;
    const float* bias = dir ? bias1 : bias0;
    const int cofs = dir * coff;
    const u32 sb = smem_u32(gsm);

    float acc[MFRAG][NFRAG][4];
    #pragma unroll
    for (int i = 0; i < MFRAG; i++)
        #pragma unroll
        for (int j = 0; j < NFRAG; j++)
            #pragma unroll
            for (int q = 0; q < 4; q++) acc[i][j][q] = 0.f;

    g2s_chunk<NT>(sb, Ahi, Alo, Whi, Wlo, bm, bn, 0, K, Nw, tid);
    asm volatile("cp.async.commit_group;" ::: "memory");

    const int nch = K / 32;
    for (int ch = 0; ch < nch; ch++) {
        asm volatile("cp.async.wait_group 0;" ::: "memory");
        __syncthreads();
        const u32 s0 = sb + (u32)(ch & 1) * STG;
        if (ch + 1 < nch) {
            g2s_chunk<NT>(sb + (u32)((ch + 1) & 1) * STG, Ahi, Alo, Whi, Wlo,
                          bm, bn, (ch + 1) * 32, K, Nw, tid);
            asm volatile("cp.async.commit_group;" ::: "memory");
        }
        const u32 saH = s0, saL = s0 + ASZ, swH = s0 + 2 * ASZ, swL = swH + WSZ;
        #pragma unroll
        for (int s = 0; s < 2; s++) {
            u32 wh[NFRAG][2], wl[NFRAG][2];
            #pragma unroll
            for (int np = 0; np < NFRAG / 2; np++) {
                u32 r0, r1, r2, r3;
                const u32 colb = 2 * (u32)(wn + np * 16 + ((lane >> 4) << 3));
                const u32 rowb = (u32)(s * 16 + (lane & 15)) * PB;
                ldsm4t(r0, r1, r2, r3, swH + rowb + colb);
                wh[2*np][0] = r0; wh[2*np][1] = r1;
                wh[2*np+1][0] = r2; wh[2*np+1][1] = r3;
                ldsm4t(r0, r1, r2, r3, swL + rowb + colb);
                wl[2*np][0] = r0; wl[2*np][1] = r1;
                wl[2*np+1][0] = r2; wl[2*np+1][1] = r3;
            }
            u32 a[MFRAG][4];
            #pragma unroll
            for (int mf = 0; mf < MFRAG; mf++)
                ldsm4(a[mf][0], a[mf][1], a[mf][2], a[mf][3],
                      saH + (u32)(wm + mf * 16 + (lane & 15)) * PA
                          + s * 32 + ((lane >> 4) << 4));
            #pragma unroll
            for (int mf = 0; mf < MFRAG; mf++)
                #pragma unroll
                for (int nf = 0; nf < NFRAG; nf++) {
                    mma_bf16(acc[mf][nf], a[mf], wh[nf]);
                    mma_bf16(acc[mf][nf], a[mf], wl[nf]);
                }
            #pragma unroll
            for (int mf = 0; mf < MFRAG; mf++)
                ldsm4(a[mf][0], a[mf][1], a[mf][2], a[mf][3],
                      saL + (u32)(wm + mf * 16 + (lane & 15)) * PA
                          + s * 32 + ((lane >> 4) << 4));
            #pragma unroll
            for (int mf = 0; mf < MFRAG; mf++)
                #pragma unroll
                for (int nf = 0; nf < NFRAG; nf++)
                    mma_bf16(acc[mf][nf], a[mf], wh[nf]);
        }
        __syncthreads();
    }

    #pragma unroll
    for (int mf = 0; mf < MFRAG; mf++) {
        #pragma unroll
        for (int nf = 0; nf < NFRAG; nf++) {
            const int r0 = bm + wm + mf * 16 + (lane >> 2);
            const int col = bn + wn + nf * 8 + (lane & 3) * 2;
            const float b0 = bias[col], b1 = bias[col + 1];
            float v00 = acc[mf][nf][0] + b0, v01 = acc[mf][nf][1] + b1;
            float v10 = acc[mf][nf][2] + b0, v11 = acc[mf][nf][3] + b1;
            if constexpr (sizeof(CT) == 2) {
                *(u32*)&C[(size_t)r0 * ldc + cofs + col]       = pkh2(v00, v01);
                *(u32*)&C[(size_t)(r0 + 8) * ldc + cofs + col] = pkh2(v10, v11);
            } else {
                *(float2*)&C[(size_t)r0 * ldc + cofs + col] = make_float2(v00, v01);
                *(float2*)&C[(size_t)(r0 + 8) * ldc + cofs + col] = make_float2(v10, v11);
            }
        }
    }
}

// ---------------------------------------------------------------------------
// Tensor-core LSTM (R15, proven): U in registers, f16 xz in.
// F16O: output h as single f16 plane (of16); else bf16 hi/lo planes.
// ---------------------------------------------------------------------------
template<int HU, bool SEQ, bool F16O>
__global__ __launch_bounds__(512, 1)
void lstm_tc(const __half* __restrict__ xz, size_t strideB, size_t strideT,
             const float* __restrict__ Uf, const float* __restrict__ Ub,
             bf16* __restrict__ ohi, bf16* __restrict__ olo,
             __half* __restrict__ of16, int ldo, int T)
{
    constexpr int NG = 4 * HU, NW = NG / 16, NFRAG = NW / 8;
    constexpr int KF = HU / 16;
    constexpr int HP = HU + 8;
    constexpr int GP = NG + 4;
    constexpr int NC = HU / 32;

    extern __shared__ char sm[];
    __half* hhi  = (__half*)sm;                     // [16*HP]
    float*  gbuf = (float*)(hhi + 16 * HP);         // [16*GP]

    const int tid = threadIdx.x, wid = tid >> 5, lane = tid & 31;
    const int g = lane >> 2, c2 = (lane & 3) * 2;
    const int dir = blockIdx.y, b0 = blockIdx.x * 16;
    const float* U    = dir ? Ub : Uf;
    const __half* xzd = xz + (size_t)dir * NG;
    bf16* ohid = ohi + dir * HU;
    bf16* olid = olo + dir * HU;
    __half* of16d = of16 + dir * HU;

    u64 ureg[KF * NFRAG];
    #pragma unroll
    for (int kf = 0; kf < KF; kf++)
        #pragma unroll
        for (int nf = 0; nf < NFRAG; nf++) {
            const int n  = (wid * NFRAG + nf) * 8 + (lane >> 2);
            const int k0 = kf * 16 + 2 * (lane & 3);
            float x0 = U[(size_t)k0 * NG + n];
            float x1 = U[(size_t)(k0 + 1) * NG + n];
            float x2 = U[(size_t)(k0 + 8) * NG + n];
            float x3 = U[(size_t)(k0 + 9) * NG + n];
            ureg[kf * NFRAG + nf] =
                pkh64(__half2float(__float2half_rn(x0)),
                      __half2float(__float2half_rn(x1)),
                      __half2float(__float2half_rn(x2)),
                      __half2float(__float2half_rn(x3)));
        }

    for (int idx = tid; idx < 16 * HP / 2; idx += 512)
        ((u32*)hhi)[idx] = 0;
    __syncthreads();

    const int gate = (wid * NW) / HU;
    const int ur = tid >> 5, uj = (tid & 31) * NC;
    float cst[NC];
    #pragma unroll
    for (int i = 0; i < NC; i++) cst[i] = 0.f;

    for (int t = 0; t < T; t++) {
        const int tt = dir ? (T - 1 - t) : t;

        u32 xvp[NFRAG][2];
        {
            const __half* xp0 = xzd + (size_t)(b0 + g) * strideB
                                + (size_t)tt * strideT + wid * NW + c2;
            const __half* xp1 = xp0 + 8 * strideB;
            #pragma unroll
            for (int nf = 0; nf < NFRAG; nf++) {
                xvp[nf][0] = *(const u32*)(xp0 + nf * 8);
                xvp[nf][1] = *(const u32*)(xp1 + nf * 8);
            }
        }

        float acc[NFRAG][4];
        #pragma unroll
        for (int nf = 0; nf < NFRAG; nf++)
            #pragma unroll
            for (int q = 0; q < 4; q++) acc[nf][q] = 0.f;

        #pragma unroll
        for (int kf = 0; kf < KF; kf++) {
            const int kb = kf * 16 + c2;
            u32 a[4];
            a[0] = *(const u32*)&hhi[g * HP + kb];
            a[1] = *(const u32*)&hhi[(g + 8) * HP + kb];
            a[2] = *(const u32*)&hhi[g * HP + kb + 8];
            a[3] = *(const u32*)&hhi[(g + 8) * HP + kb + 8];
            #pragma unroll
            for (int nf = 0; nf < NFRAG; nf++) {
                u64 b = ureg[kf * NFRAG + nf];
                mma_f16(acc[nf], a, (u32)b, (u32)(b >> 32));
            }
        }

        #pragma unroll
        for (int nf = 0; nf < NFRAG; nf++) {
            const int n = wid * NW + nf * 8 + c2;
            float2 x0 = __half22float2(*(const __half2*)&xvp[nf][0]);
            float2 x1 = __half22float2(*(const __half2*)&xvp[nf][1]);
            float z0 = acc[nf][0] + x0.x, z1 = acc[nf][1] + x0.y;
            float z2 = acc[nf][2] + x1.x, z3 = acc[nf][3] + x1.y;
            float2 w0, w1;
            if (gate == 2) {
                w0 = make_float2(fmaxf(z0, 0.f), fmaxf(z1, 0.f));
                w1 = make_float2(fmaxf(z2, 0.f), fmaxf(z3, 0.f));
            } else {
                w0 = make_float2(sigm(z0), sigm(z1));
                w1 = make_float2(sigm(z2), sigm(z3));
            }
            *(float2*)&gbuf[g * GP + n]       = w0;
            *(float2*)&gbuf[(g + 8) * GP + n] = w1;
        }
        __syncthreads();

        {
            float iv[NC], fv[NC], gv[NC], ov[NC], ho[NC];
            const float* gb = gbuf + ur * GP + uj;
            if constexpr (NC == 4) {
                *(float4*)iv = *(const float4*)(gb);
                *(float4*)fv = *(const float4*)(gb + HU);
                *(float4*)gv = *(const float4*)(gb + 2 * HU);
                *(float4*)ov = *(const float4*)(gb + 3 * HU);
            } else {
                *(float2*)iv = *(const float2*)(gb);
                *(float2*)fv = *(const float2*)(gb + HU);
                *(float2*)gv = *(const float2*)(gb + 2 * HU);
                *(float2*)ov = *(const float2*)(gb + 3 * HU);
            }
            #pragma unroll
            for (int i = 0; i < NC; i++) {
                cst[i] = fv[i] * cst[i] + iv[i] * gv[i];
                ho[i] = ov[i] * fmaxf(cst[i], 0.f);
            }
            u32 hw[NC / 2];
            #pragma unroll
            for (int q = 0; q < NC / 2; q++)
                hw[q] = pkh2(ho[2 * q], ho[2 * q + 1]);

            if (SEQ || t == T - 1) {
                size_t idx = SEQ ? (((size_t)(b0 + ur) * T + tt) * ldo + uj)
                                 : ((size_t)(b0 + ur) * ldo + uj);
                if constexpr (F16O) {
                    if constexpr (NC == 4)
                        *(uint2*)(of16d + idx) = make_uint2(hw[0], hw[1]);
                    else
                        *(u32*)(of16d + idx) = hw[0];
                } else {
                    u32 hw0 = pkbf(ho[0], ho[1]);
                    u32 lw0 = pkbf(bres(ho[0]), bres(ho[1]));
                    if constexpr (NC == 4) {
                        u32 hw1 = pkbf(ho[2], ho[3]);
                        u32 lw1 = pkbf(bres(ho[2]), bres(ho[3]));
                        *(uint2*)(ohid + idx) = make_uint2(hw0, hw1);
                        *(uint2*)(olid + idx) = make_uint2(lw0, lw1);
                    } else {
                        *(u32*)(ohid + idx) = hw0;
                        *(u32*)(olid + idx) = lw0;
                    }
                }
            }
            u32* hp = (u32*)&hhi[ur * HP + uj];
            if constexpr (NC == 4)
                *(uint2*)hp = make_uint2(hw[0], hw[1]);
            else
                hp[0] = hw[0];
        }
        __syncthreads();
    }
}

// ---------------------------------------------------------------------------
extern "C" void kernel_launch(void* const* d_in, const int* in_sizes, int n_in,
                              void* d_out, int out_size)
{
    const float* x    = (const float*)d_in[0];
    const float* e1fW = (const float*)d_in[1];
    const float* e1fU = (const float*)d_in[2];
    const float* e1fb = (const float*)d_in[3];
    const float* e1bW = (const float*)d_in[4];
    const float* e1bU = (const float*)d_in[5];
    const float* e1bb = (const float*)d_in[6];
    const float* e2fW = (const float*)d_in[7];
    const float* e2fU = (const float*)d_in[8];
    const float* e2fb = (const float*)d_in[9];
    const float* e2bW = (const float*)d_in[10];
    const float* e2bU = (const float*)d_in[11];
    const float* e2bb = (const float*)d_in[12];
    const float* d1fW = (const float*)d_in[13];
    const float* d1fU = (const float*)d_in[14];
    const float* d1fb = (const float*)d_in[15];
    const float* d1bW = (const float*)d_in[16];
    const float* d1bU = (const float*)d_in[17];
    const float* d1bb = (const float*)d_in[18];
    const float* d2fW = (const float*)d_in[19];
    const float* d2fU = (const float*)d_in[20];
    const float* d2fb = (const float*)d_in[21];
    const float* d2bW = (const float*)d_in[22];
    const float* d2bU = (const float*)d_in[23];
    const float* d2bb = (const float*)d_in[24];
    const float* Wd   = (const float*)d_in[25];
    const float* bd   = (const float*)d_in[26];

    float *p1, *p2, *p3;
    bf16 *xf, *h1hi, *h1lo, *hd1f, *zhi, *zlo, *whi, *wlo;
    __half* wf;
    cudaGetSymbolAddress((void**)&p1,    g_xz1);
    cudaGetSymbolAddress((void**)&p2,    g_xz2);
    cudaGetSymbolAddress((void**)&p3,    g_xzd1);
    cudaGetSymbolAddress((void**)&xf,    g_xf);
    cudaGetSymbolAddress((void**)&h1hi,  g_h1hi);
    cudaGetSymbolAddress((void**)&h1lo,  g_h1lo);
    cudaGetSymbolAddress((void**)&hd1f,  g_hd1f);
    cudaGetSymbolAddress((void**)&zhi,   g_zhi);
    cudaGetSymbolAddress((void**)&zlo,   g_zlo);
    cudaGetSymbolAddress((void**)&whi,   g_whi);
    cudaGetSymbolAddress((void**)&wlo,   g_wlo);
    cudaGetSymbolAddress((void**)&wf,    g_wf);
    __half* xz1  = (__half*)p1;
    __half* xz2  = (__half*)p2;
    __half* xzd1 = (__half*)p3;
    __half* xf16  = (__half*)xf;
    __half* hd1f16 = (__half*)hd1f;

    // bf16 plane offsets (only e2/d1/dense used now, layout unchanged)
    const int O_e2f = 65536,  O_e2b = 131072;
    const int O_d1f = 196608, O_d1b = 229376;
    const int O_wd  = 393216;
    // f16 weight offsets: e1f=0, e1b=32768, d2f=65536, d2b=131072
    const int F_e1f = 0, F_e1b = 32768, F_d2f = 65536, F_d2b = 131072;

    const int LS128 = 16 * 136 * 2 + 16 * 516 * 4;
    const int LS64  = 16 * 72 * 2 + 16 * 260 * 4;
    cudaFuncSetAttribute(lstm_tc<128, true, false>,
                         cudaFuncAttributeMaxDynamicSharedMemorySize, LS128);
    cudaFuncSetAttribute(lstm_tc<64, false, false>,
                         cudaFuncAttributeMaxDynamicSharedMemorySize, LS64);
    cudaFuncSetAttribute(lstm_tc<64, true, true>,
                         cudaFuncAttributeMaxDynamicSharedMemorySize, LS64);

    const int GS128 = 2 * (2 * 128 * 80 + 2 * 32 * 272);
    const int GS64  = 2 * (2 * 128 * 80 + 2 * 32 * 144);
    const int G1S   = 2 * (128 * 80 + 32 * 272);   // 37888
    cudaFuncSetAttribute(hgemm2<128, 2, 4, __half>,
                         cudaFuncAttributeMaxDynamicSharedMemorySize, GS128);
    cudaFuncSetAttribute(hgemm2<64, 4, 2, float>,
                         cudaFuncAttributeMaxDynamicSharedMemorySize, GS64);
    cudaFuncSetAttribute(hgemm1<128, 2, 4>,
                         cudaFuncAttributeMaxDynamicSharedMemorySize, G1S);

    const int T = 256;

    cvt_x16<<<2048, 256>>>(x, xf16, 2097152);
    cvt_wf<<<192, 256>>>(e1fW, e1bW, d2fW, d2bW, wf);
    cvt_w9<<<256, 256>>>(e1fW, e1bW, e2fW, e2bW, d1fW, d1bW, d2fW, d2bW, Wd,
                         whi, wlo);

    // e1 (K=64, Nw=512, both dirs) — single-term f16
    hgemm1<128, 2, 4><<<dim3(4, 1024, 2), 256, G1S>>>(
        xf16, wf + F_e1f, wf + F_e1b, e1fb, e1bb, xz1, 64, 512, 1024, 512);
    lstm_tc<128, true, false><<<dim3(32, 2), 512, LS128>>>(
        xz1, (size_t)T * 1024, 1024, e1fU, e1bU, h1hi, h1lo, nullptr, 256, T);

    // e2 (K=256, Nw=256) — 3-term bf16
    hgemm2<128, 2, 4, __half><<<dim3(2, 1024, 2), 256, GS128>>>(
        h1hi, h1lo, whi + O_e2f, wlo + O_e2f, whi + O_e2b, wlo + O_e2b,
        e2fb, e2bb, xz2, 256, 256, 512, 256);
    lstm_tc<64, false, false><<<dim3(32, 2), 512, LS64>>>(
        xz2, (size_t)T * 512, 512, e2fU, e2bU, zhi, zlo, nullptr, 128, T);

    // d1 (M=512, K=128, Nw=256) — 3-term bf16 (tiny)
    hgemm2<128, 2, 4, __half><<<dim3(2, 4, 2), 256, GS128>>>(
        zhi, zlo, whi + O_d1f, wlo + O_d1f, whi + O_d1b, wlo + O_d1b,
        d1fb, d1bb, xzd1, 128, 256, 512, 256);
    lstm_tc<64, true, true><<<dim3(32, 2), 512, LS64>>>(
        xzd1, 512, 0, d1fU, d1bU, nullptr, nullptr, hd1f16, 128, T);

    // d2 (K=128, Nw=512) — single-term f16
    hgemm1<128, 2, 4><<<dim3(4, 1024, 2), 256, G1S>>>(
        hd1f16, wf + F_d2f, wf + F_d2b, d2fb, d2bb, xz1, 128, 512, 1024, 512);
    lstm_tc<128, true, false><<<dim3(32, 2), 512, LS128>>>(
        xz1, (size_t)T * 1024, 1024, d2fU, d2bU, h1hi, h1lo, nullptr, 256, T);

    // dense (K=256, Nw=64, single dir, fp32 out) — 3-term bf16
    hgemm2<64, 4, 2, float><<<dim3(1, 1024, 1), 256, GS64>>>(
        h1hi, h1lo, whi + O_wd, wlo + O_wd, whi + O_wd, wlo + O_wd,
        bd, bd, (float*)d_out, 256, 64, 64, 0);
}

// round 17
// speedup vs baseline: 2.2143x; 1.2118x over previous
#include <cuda_runtime.h>
#include <cuda_bf16.h>
#include <cuda_fp16.h>
#include <math.h>
#include <stdint.h>

#define BT 131072
typedef unsigned long long u64;
typedef unsigned int u32;
typedef __nv_bfloat16 bf16;

// scratch (g_xz* reinterpreted as half planes)
__device__ float g_xz1 [67108864];    // as half: [BT,1024]
__device__ float g_xz2 [33554432];    // as half: [BT, 512]
__device__ float g_xzd1[131072];      // as half: [B, 512]
// operand planes
__device__ bf16 g_xf   [8388608];     // x   f16 [BT,64]   (as __half)
__device__ bf16 g_h1f  [33554432];    // h1  f16 [BT,256]  (as __half)
__device__ bf16 g_hd1f [16777216];    // hd1 f16 [BT,128]  (as __half)
__device__ bf16 g_zhi  [65536],  g_zlo [65536];   // z bf16 hi/lo
__device__ bf16 g_whi  [65536],  g_wlo [65536];   // bf16 planes (d1f,d1b)
__device__ __half g_wf [344064];      // f16 weights: e1f,e1b,e2f,e2b,d2f,d2b,Wd

__device__ __forceinline__ float sigm(float x) {
    return __fdividef(1.0f, 1.0f + __expf(-x));
}
__device__ __forceinline__ u32 smem_u32(const void* p) {
    u32 a; asm("{ .reg .u64 t; cvta.to.shared.u64 t, %1; cvt.u32.u64 %0, t; }"
               : "=r"(a) : "l"(p));
    return a;
}
__device__ __forceinline__ u32 pkbf(float a, float b) {
    __nv_bfloat162 t = __floats2bfloat162_rn(a, b);
    return *reinterpret_cast<u32*>(&t);
}
__device__ __forceinline__ float bres(float x) {
    return x - __bfloat162float(__float2bfloat16_rn(x));
}
__device__ __forceinline__ u32 pkh2(float a, float b) {
    __half2 h = __floats2half2_rn(a, b);
    return *reinterpret_cast<u32*>(&h);
}
__device__ __forceinline__ u64 pkh64(float a, float b, float c, float d) {
    return (u64)pkh2(a, b) | ((u64)pkh2(c, d) << 32);
}
__device__ __forceinline__ void ldsm4(u32 &r0, u32 &r1, u32 &r2, u32 &r3, u32 a) {
    asm volatile("ldmatrix.sync.aligned.m8n8.x4.shared.b16 {%0,%1,%2,%3}, [%4];"
                 : "=r"(r0), "=r"(r1), "=r"(r2), "=r"(r3) : "r"(a));
}
__device__ __forceinline__ void ldsm4t(u32 &r0, u32 &r1, u32 &r2, u32 &r3, u32 a) {
    asm volatile("ldmatrix.sync.aligned.m8n8.x4.trans.shared.b16 {%0,%1,%2,%3}, [%4];"
                 : "=r"(r0), "=r"(r1), "=r"(r2), "=r"(r3) : "r"(a));
}
__device__ __forceinline__ void mma_bf16(float* c, const u32* a, const u32* b) {
    asm volatile("mma.sync.aligned.m16n8k16.row.col.f32.bf16.bf16.f32 "
                 "{%0,%1,%2,%3}, {%4,%5,%6,%7}, {%8,%9}, {%0,%1,%2,%3};"
                 : "+f"(c[0]), "+f"(c[1]), "+f"(c[2]), "+f"(c[3])
                 : "r"(a[0]), "r"(a[1]), "r"(a[2]), "r"(a[3]), "r"(b[0]), "r"(b[1]));
}
__device__ __forceinline__ void mma_f16(float* c, const u32* a, u32 b0, u32 b1) {
    asm volatile("mma.sync.aligned.m16n8k16.row.col.f32.f16.f16.f32 "
                 "{%0,%1,%2,%3}, {%4,%5,%6,%7}, {%8,%9}, {%0,%1,%2,%3};"
                 : "+f"(c[0]), "+f"(c[1]), "+f"(c[2]), "+f"(c[3])
                 : "r"(a[0]), "r"(a[1]), "r"(a[2]), "r"(a[3]), "r"(b0), "r"(b1));
}
__device__ __forceinline__ void cp16(u32 d, const void* s) {
    asm volatile("cp.async.ca.shared.global [%0], [%1], 16;" :: "r"(d), "l"(s));
}
__device__ __forceinline__ void cp8(u32 d, const void* s) {
    asm volatile("cp.async.ca.shared.global [%0], [%1], 8;" :: "r"(d), "l"(s));
}

// ---------------------------------------------------------------------------
// Converters
// ---------------------------------------------------------------------------
__global__ void cvt_x16(const float* __restrict__ s, __half* __restrict__ o, int n4)
{
    for (int i = blockIdx.x * blockDim.x + threadIdx.x; i < n4;
         i += gridDim.x * blockDim.x) {
        float4 v = ((const float4*)s)[i];
        ((uint2*)o)[i] = make_uint2(pkh2(v.x, v.y), pkh2(v.z, v.w));
    }
}

__global__ void cvt_wf7(const float* w0, const float* w1, const float* w2,
                        const float* w3, const float* w4, const float* w5,
                        const float* w6, __half* __restrict__ o)
{
    const int off[8] = {0, 8192, 16384, 32768, 49152, 65536, 81920, 86016};
    const float* ws[7] = {w0, w1, w2, w3, w4, w5, w6};
    for (int i = blockIdx.x * blockDim.x + threadIdx.x; i < 86016;
         i += gridDim.x * blockDim.x) {
        int s = 0;
        #pragma unroll
        for (int k = 1; k < 7; k++) if (i >= off[k]) s = k;
        float4 v = ((const float4*)ws[s])[i - off[s]];
        ((uint2*)o)[i] = make_uint2(pkh2(v.x, v.y), pkh2(v.z, v.w));
    }
}

__global__ void cvt_w2(const float* w0, const float* w1,
                       bf16* __restrict__ hi, bf16* __restrict__ lo)
{
    for (int i = blockIdx.x * blockDim.x + threadIdx.x; i < 16384;
         i += gridDim.x * blockDim.x) {
        const float* W = (i < 8192) ? w0 : w1;
        float4 v = ((const float4*)W)[i & 8191];
        ((uint2*)hi)[i] = make_uint2(pkbf(v.x, v.y), pkbf(v.z, v.w));
        ((uint2*)lo)[i] = make_uint2(pkbf(bres(v.x), bres(v.y)),
                                     pkbf(bres(v.z), bres(v.w)));
    }
}

// ---------------------------------------------------------------------------
// hgemm1: single-term f16 GEMM. C = A(f16) @ W(f16) + bias.
// ---------------------------------------------------------------------------
template<int NT, int WM, int WN, typename CT>
__global__ __launch_bounds__(256, 2)
void hgemm1(const __half* __restrict__ A,
            const __half* __restrict__ W0, const __half* __restrict__ W1,
            const float* __restrict__ bias0, const float* __restrict__ bias1,
            CT* __restrict__ C, int K, int Nw, int ldc, int coff)
{
    constexpr int PA = 80, ASZ = 128 * PA;
    constexpr int PB = NT * 2 + 16, WSZ = 32 * PB;
    constexpr int STG = ASZ + WSZ;
    constexpr int MW = 128 / WM, NWT = NT / WN;
    constexpr int MFRAG = MW / 16, NFRAG = NWT / 8;
    constexpr int WB = (NT / 8) * 2;     // W bytes per loader thread (32 or 16)
    extern __shared__ char gsm[];

    const int tid = threadIdx.x, wid = tid >> 5, lane = tid & 31;
    const int bm = blockIdx.y * 128, bn = blockIdx.x * NT, dir = blockIdx.z;
    const int wm = (wid / WN) * MW, wn = (wid % WN) * NWT;
    const __half* W = dir ? W1 : W0;
    const float* bias = dir ? bias1 : bias0;
    const int cofs = dir * coff;
    const u32 sb = smem_u32(gsm);

    float acc[MFRAG][NFRAG][4];
    #pragma unroll
    for (int i = 0; i < MFRAG; i++)
        #pragma unroll
        for (int j = 0; j < NFRAG; j++)
            #pragma unroll
            for (int q = 0; q < 4; q++) acc[i][j][q] = 0.f;

    const int ar = tid >> 1, ah = (tid & 1);
    const int wr = tid >> 3, wsg = (tid & 7);

    auto g2s = [&](u32 base, int k0) {
        const __half* as = A + (size_t)(bm + ar) * K + k0 + ah * 16;
        u32 ad = base + ar * PA + ah * 32;
        cp16(ad, as);
        cp16(ad + 16, as + 8);
        const __half* wsrc = W + (size_t)(k0 + wr) * Nw + bn + wsg * (WB / 2);
        u32 wd = base + ASZ + wr * PB + wsg * WB;
        cp16(wd, wsrc);
        if (WB == 32) cp16(wd + 16, wsrc + 8);
    };

    g2s(sb, 0);
    asm volatile("cp.async.commit_group;" ::: "memory");

    const int nch = K / 32;
    for (int ch = 0; ch < nch; ch++) {
        asm volatile("cp.async.wait_group 0;" ::: "memory");
        __syncthreads();
        const u32 s0 = sb + (u32)(ch & 1) * STG;
        if (ch + 1 < nch) {
            g2s(sb + (u32)((ch + 1) & 1) * STG, (ch + 1) * 32);
            asm volatile("cp.async.commit_group;" ::: "memory");
        }
        const u32 sa = s0, sw = s0 + ASZ;
        #pragma unroll
        for (int s = 0; s < 2; s++) {
            u32 wf[NFRAG][2];
            #pragma unroll
            for (int np = 0; np < NFRAG / 2; np++) {
                u32 r0, r1, r2, r3;
                ldsm4t(r0, r1, r2, r3,
                       sw + (u32)(s * 16 + (lane & 15)) * PB
                          + 2 * (u32)(wn + np * 16 + ((lane >> 4) << 3)));
                wf[2*np][0] = r0; wf[2*np][1] = r1;
                wf[2*np+1][0] = r2; wf[2*np+1][1] = r3;
            }
            u32 a[MFRAG][4];
            #pragma unroll
            for (int mf = 0; mf < MFRAG; mf++)
                ldsm4(a[mf][0], a[mf][1], a[mf][2], a[mf][3],
                      sa + (u32)(wm + mf * 16 + (lane & 15)) * PA
                         + s * 32 + ((lane >> 4) << 4));
            #pragma unroll
            for (int mf = 0; mf < MFRAG; mf++)
                #pragma unroll
                for (int nf = 0; nf < NFRAG; nf++)
                    mma_f16(acc[mf][nf], a[mf], wf[nf][0], wf[nf][1]);
        }
        __syncthreads();
    }

    #pragma unroll
    for (int mf = 0; mf < MFRAG; mf++) {
        #pragma unroll
        for (int nf = 0; nf < NFRAG; nf++) {
            const int r0 = bm + wm + mf * 16 + (lane >> 2);
            const int col = bn + wn + nf * 8 + (lane & 3) * 2;
            const float b0 = bias[col], b1 = bias[col + 1];
            float v00 = acc[mf][nf][0] + b0, v01 = acc[mf][nf][1] + b1;
            float v10 = acc[mf][nf][2] + b0, v11 = acc[mf][nf][3] + b1;
            if constexpr (sizeof(CT) == 2) {
                *(u32*)&C[(size_t)r0 * ldc + cofs + col]       = pkh2(v00, v01);
                *(u32*)&C[(size_t)(r0 + 8) * ldc + cofs + col] = pkh2(v10, v11);
            } else {
                *(float2*)&C[(size_t)r0 * ldc + cofs + col] = make_float2(v00, v01);
                *(float2*)&C[(size_t)(r0 + 8) * ldc + cofs + col] = make_float2(v10, v11);
            }
        }
    }
}

// ---------------------------------------------------------------------------
// hgemm2 (3-term bf16, proven) — only d1 uses it now.
// ---------------------------------------------------------------------------
template<int NT>
__device__ __forceinline__ void g2s_chunk(
    u32 sbase, const bf16* Ahi, const bf16* Alo,
    const bf16* Whi, const bf16* Wlo,
    int bm, int bn, int k0, int K, int Nw, int tid)
{
    constexpr int PA = 80, ASZ = 128 * PA;
    constexpr int PB = NT * 2 + 16, WSZ = 32 * PB;
    constexpr int WOPS = NT / 32;
    {
        int row = tid & 127;
        const bf16* src = ((tid & 128) ? Alo : Ahi) + (size_t)(bm + row) * K + k0;
        u32 dst = sbase + ((tid & 128) ? ASZ : 0) + row * PA;
        #pragma unroll
        for (int i = 0; i < 8; i++)
            cp8(dst + i * 8, (const char*)src + i * 8);
    }
    {
        int idx = tid & 127, row = idx >> 2, seg = idx & 3;
        const bf16* src = ((tid & 128) ? Wlo : Whi)
                          + (size_t)(k0 + row) * Nw + bn + seg * (NT / 4);
        u32 dst = sbase + 2 * ASZ + ((tid & 128) ? WSZ : 0) + row * PB + seg * (NT / 2);
        #pragma unroll
        for (int i = 0; i < WOPS; i++)
            cp16(dst + i * 16, (const char*)src + i * 16);
    }
}

template<int NT, int WM, int WN, typename CT>
__global__ __launch_bounds__(256, 2)
void hgemm2(const bf16* __restrict__ Ahi, const bf16* __restrict__ Alo,
            const bf16* __restrict__ Whi0, const bf16* __restrict__ Wlo0,
            const bf16* __restrict__ Whi1, const bf16* __restrict__ Wlo1,
            const float* __restrict__ bias0, const float* __restrict__ bias1,
            CT* __restrict__ C, int K, int Nw, int ldc, int coff)
{
    constexpr int PA = 80, ASZ = 128 * PA;
    constexpr int PB = NT * 2 + 16, WSZ = 32 * PB;
    constexpr int STG = 2 * ASZ + 2 * WSZ;
    constexpr int MW = 128 / WM, NWT = NT / WN;
    constexpr int MFRAG = MW / 16, NFRAG = NWT / 8;
    extern __shared__ char gsm[];

    const int tid = threadIdx.x, wid = tid >> 5, lane = tid & 31;
    const int bm = blockIdx.y * 128, bn = blockIdx.x * NT, dir = blockIdx.z;
    const int wm = (wid / WN) * MW, wn = (wid % WN) * NWT;
    const bf16* Whi = dir ? Whi1 : Whi0;
    const bf16* Wlo = dir ? Wlo1 : Wlo0;
    const float* bias = dir ? bias1 : bias0;
    const int cofs = dir * coff;
    const u32 sb = smem_u32(gsm);

    float acc[MFRAG][NFRAG][4];
    #pragma unroll
    for (int i = 0; i < MFRAG; i++)
        #pragma unroll
        for (int j = 0; j < NFRAG; j++)
            #pragma unroll
            for (int q = 0; q < 4; q++) acc[i][j][q] = 0.f;

    g2s_chunk<NT>(sb, Ahi, Alo, Whi, Wlo, bm, bn, 0, K, Nw, tid);
    asm volatile("cp.async.commit_group;" ::: "memory");

    const int nch = K / 32;
    for (int ch = 0; ch < nch; ch++) {
        asm volatile("cp.async.wait_group 0;" ::: "memory");
        __syncthreads();
        const u32 s0 = sb + (u32)(ch & 1) * STG;
        if (ch + 1 < nch) {
            g2s_chunk<NT>(sb + (u32)((ch + 1) & 1) * STG, Ahi, Alo, Whi, Wlo,
                          bm, bn, (ch + 1) * 32, K, Nw, tid);
            asm volatile("cp.async.commit_group;" ::: "memory");
        }
        const u32 saH = s0, saL = s0 + ASZ, swH = s0 + 2 * ASZ, swL = swH + WSZ;
        #pragma unroll
        for (int s = 0; s < 2; s++) {
            u32 wh[NFRAG][2], wl[NFRAG][2];
            #pragma unroll
            for (int np = 0; np < NFRAG / 2; np++) {
                u32 r0, r1, r2, r3;
                const u32 colb = 2 * (u32)(wn + np * 16 + ((lane >> 4) << 3));
                const u32 rowb = (u32)(s * 16 + (lane & 15)) * PB;
                ldsm4t(r0, r1, r2, r3, swH + rowb + colb);
                wh[2*np][0] = r0; wh[2*np][1] = r1;
                wh[2*np+1][0] = r2; wh[2*np+1][1] = r3;
                ldsm4t(r0, r1, r2, r3, swL + rowb + colb);
                wl[2*np][0] = r0; wl[2*np][1] = r1;
                wl[2*np+1][0] = r2; wl[2*np+1][1] = r3;
            }
            u32 a[MFRAG][4];
            #pragma unroll
            for (int mf = 0; mf < MFRAG; mf++)
                ldsm4(a[mf][0], a[mf][1], a[mf][2], a[mf][3],
                      saH + (u32)(wm + mf * 16 + (lane & 15)) * PA
                          + s * 32 + ((lane >> 4) << 4));
            #pragma unroll
            for (int mf = 0; mf < MFRAG; mf++)
                #pragma unroll
                for (int nf = 0; nf < NFRAG; nf++) {
                    mma_bf16(acc[mf][nf], a[mf], wh[nf]);
                    mma_bf16(acc[mf][nf], a[mf], wl[nf]);
                }
            #pragma unroll
            for (int mf = 0; mf < MFRAG; mf++)
                ldsm4(a[mf][0], a[mf][1], a[mf][2], a[mf][3],
                      saL + (u32)(wm + mf * 16 + (lane & 15)) * PA
                          + s * 32 + ((lane >> 4) << 4));
            #pragma unroll
            for (int mf = 0; mf < MFRAG; mf++)
                #pragma unroll
                for (int nf = 0; nf < NFRAG; nf++)
                    mma_bf16(acc[mf][nf], a[mf], wh[nf]);
        }
        __syncthreads();
    }

    #pragma unroll
    for (int mf = 0; mf < MFRAG; mf++) {
        #pragma unroll
        for (int nf = 0; nf < NFRAG; nf++) {
            const int r0 = bm + wm + mf * 16 + (lane >> 2);
            const int col = bn + wn + nf * 8 + (lane & 3) * 2;
            const float b0 = bias[col], b1 = bias[col + 1];
            float v00 = acc[mf][nf][0] + b0, v01 = acc[mf][nf][1] + b1;
            float v10 = acc[mf][nf][2] + b0, v11 = acc[mf][nf][3] + b1;
            if constexpr (sizeof(CT) == 2) {
                *(u32*)&C[(size_t)r0 * ldc + cofs + col]       = pkh2(v00, v01);
                *(u32*)&C[(size_t)(r0 + 8) * ldc + cofs + col] = pkh2(v10, v11);
            } else {
                *(float2*)&C[(size_t)r0 * ldc + cofs + col] = make_float2(v00, v01);
                *(float2*)&C[(size_t)(r0 + 8) * ldc + cofs + col] = make_float2(v10, v11);
            }
        }
    }
}

// ---------------------------------------------------------------------------
// Tensor-core LSTM (R15 proven): U in registers, f16 xz in.
// F16O: output h as single f16 plane; else bf16 hi/lo planes.
// ---------------------------------------------------------------------------
template<int HU, bool SEQ, bool F16O>
__global__ __launch_bounds__(512, 1)
void lstm_tc(const __half* __restrict__ xz, size_t strideB, size_t strideT,
             const float* __restrict__ Uf, const float* __restrict__ Ub,
             bf16* __restrict__ ohi, bf16* __restrict__ olo,
             __half* __restrict__ of16, int ldo, int T)
{
    constexpr int NG = 4 * HU, NW = NG / 16, NFRAG = NW / 8;
    constexpr int KF = HU / 16;
    constexpr int HP = HU + 8;
    constexpr int GP = NG + 4;
    constexpr int NC = HU / 32;

    extern __shared__ char sm[];
    __half* hhi  = (__half*)sm;                     // [16*HP]
    float*  gbuf = (float*)(hhi + 16 * HP);         // [16*GP]

    const int tid = threadIdx.x, wid = tid >> 5, lane = tid & 31;
    const int g = lane >> 2, c2 = (lane & 3) * 2;
    const int dir = blockIdx.y, b0 = blockIdx.x * 16;
    const float* U    = dir ? Ub : Uf;
    const __half* xzd = xz + (size_t)dir * NG;
    bf16* ohid = ohi + dir * HU;
    bf16* olid = olo + dir * HU;
    __half* of16d = of16 + dir * HU;

    u64 ureg[KF * NFRAG];
    #pragma unroll
    for (int kf = 0; kf < KF; kf++)
        #pragma unroll
        for (int nf = 0; nf < NFRAG; nf++) {
            const int n  = (wid * NFRAG + nf) * 8 + (lane >> 2);
            const int k0 = kf * 16 + 2 * (lane & 3);
            float x0 = U[(size_t)k0 * NG + n];
            float x1 = U[(size_t)(k0 + 1) * NG + n];
            float x2 = U[(size_t)(k0 + 8) * NG + n];
            float x3 = U[(size_t)(k0 + 9) * NG + n];
            ureg[kf * NFRAG + nf] =
                pkh64(__half2float(__float2half_rn(x0)),
                      __half2float(__float2half_rn(x1)),
                      __half2float(__float2half_rn(x2)),
                      __half2float(__float2half_rn(x3)));
        }

    for (int idx = tid; idx < 16 * HP / 2; idx += 512)
        ((u32*)hhi)[idx] = 0;
    __syncthreads();

    const int gate = (wid * NW) / HU;
    const int ur = tid >> 5, uj = (tid & 31) * NC;
    float cst[NC];
    #pragma unroll
    for (int i = 0; i < NC; i++) cst[i] = 0.f;

    for (int t = 0; t < T; t++) {
        const int tt = dir ? (T - 1 - t) : t;

        u32 xvp[NFRAG][2];
        {
            const __half* xp0 = xzd + (size_t)(b0 + g) * strideB
                                + (size_t)tt * strideT + wid * NW + c2;
            const __half* xp1 = xp0 + 8 * strideB;
            #pragma unroll
            for (int nf = 0; nf < NFRAG; nf++) {
                xvp[nf][0] = *(const u32*)(xp0 + nf * 8);
                xvp[nf][1] = *(const u32*)(xp1 + nf * 8);
            }
        }

        float acc[NFRAG][4];
        #pragma unroll
        for (int nf = 0; nf < NFRAG; nf++)
            #pragma unroll
            for (int q = 0; q < 4; q++) acc[nf][q] = 0.f;

        #pragma unroll
        for (int kf = 0; kf < KF; kf++) {
            const int kb = kf * 16 + c2;
            u32 a[4];
            a[0] = *(const u32*)&hhi[g * HP + kb];
            a[1] = *(const u32*)&hhi[(g + 8) * HP + kb];
            a[2] = *(const u32*)&hhi[g * HP + kb + 8];
            a[3] = *(const u32*)&hhi[(g + 8) * HP + kb + 8];
            #pragma unroll
            for (int nf = 0; nf < NFRAG; nf++) {
                u64 b = ureg[kf * NFRAG + nf];
                mma_f16(acc[nf], a, (u32)b, (u32)(b >> 32));
            }
        }

        #pragma unroll
        for (int nf = 0; nf < NFRAG; nf++) {
            const int n = wid * NW + nf * 8 + c2;
            float2 x0 = __half22float2(*(const __half2*)&xvp[nf][0]);
            float2 x1 = __half22float2(*(const __half2*)&xvp[nf][1]);
            float z0 = acc[nf][0] + x0.x, z1 = acc[nf][1] + x0.y;
            float z2 = acc[nf][2] + x1.x, z3 = acc[nf][3] + x1.y;
            float2 w0, w1;
            if (gate == 2) {
                w0 = make_float2(fmaxf(z0, 0.f), fmaxf(z1, 0.f));
                w1 = make_float2(fmaxf(z2, 0.f), fmaxf(z3, 0.f));
            } else {
                w0 = make_float2(sigm(z0), sigm(z1));
                w1 = make_float2(sigm(z2), sigm(z3));
            }
            *(float2*)&gbuf[g * GP + n]       = w0;
            *(float2*)&gbuf[(g + 8) * GP + n] = w1;
        }
        __syncthreads();

        {
            float iv[NC], fv[NC], gv[NC], ov[NC], ho[NC];
            const float* gb = gbuf + ur * GP + uj;
            if constexpr (NC == 4) {
                *(float4*)iv = *(const float4*)(gb);
                *(float4*)fv = *(const float4*)(gb + HU);
                *(float4*)gv = *(const float4*)(gb + 2 * HU);
                *(float4*)ov = *(const float4*)(gb + 3 * HU);
            } else {
                *(float2*)iv = *(const float2*)(gb);
                *(float2*)fv = *(const float2*)(gb + HU);
                *(float2*)gv = *(const float2*)(gb + 2 * HU);
                *(float2*)ov = *(const float2*)(gb + 3 * HU);
            }
            #pragma unroll
            for (int i = 0; i < NC; i++) {
                cst[i] = fv[i] * cst[i] + iv[i] * gv[i];
                ho[i] = ov[i] * fmaxf(cst[i], 0.f);
            }
            u32 hw[NC / 2];
            #pragma unroll
            for (int q = 0; q < NC / 2; q++)
                hw[q] = pkh2(ho[2 * q], ho[2 * q + 1]);

            if (SEQ || t == T - 1) {
                size_t idx = SEQ ? (((size_t)(b0 + ur) * T + tt) * ldo + uj)
                                 : ((size_t)(b0 + ur) * ldo + uj);
                if constexpr (F16O) {
                    if constexpr (NC == 4)
                        *(uint2*)(of16d + idx) = make_uint2(hw[0], hw[1]);
                    else
                        *(u32*)(of16d + idx) = hw[0];
                } else {
                    u32 hw0 = pkbf(ho[0], ho[1]);
                    u32 lw0 = pkbf(bres(ho[0]), bres(ho[1]));
                    if constexpr (NC == 4) {
                        u32 hw1 = pkbf(ho[2], ho[3]);
                        u32 lw1 = pkbf(bres(ho[2]), bres(ho[3]));
                        *(uint2*)(ohid + idx) = make_uint2(hw0, hw1);
                        *(uint2*)(olid + idx) = make_uint2(lw0, lw1);
                    } else {
                        *(u32*)(ohid + idx) = hw0;
                        *(u32*)(olid + idx) = lw0;
                    }
                }
            }
            u32* hp = (u32*)&hhi[ur * HP + uj];
            if constexpr (NC == 4)
                *(uint2*)hp = make_uint2(hw[0], hw[1]);
            else
                hp[0] = hw[0];
        }
        __syncthreads();
    }
}

// ---------------------------------------------------------------------------
extern "C" void kernel_launch(void* const* d_in, const int* in_sizes, int n_in,
                              void* d_out, int out_size)
{
    const float* x    = (const float*)d_in[0];
    const float* e1fW = (const float*)d_in[1];
    const float* e1fU = (const float*)d_in[2];
    const float* e1fb = (const float*)d_in[3];
    const float* e1bW = (const float*)d_in[4];
    const float* e1bU = (const float*)d_in[5];
    const float* e1bb = (const float*)d_in[6];
    const float* e2fW = (const float*)d_in[7];
    const float* e2fU = (const float*)d_in[8];
    const float* e2fb = (const float*)d_in[9];
    const float* e2bW = (const float*)d_in[10];
    const float* e2bU = (const float*)d_in[11];
    const float* e2bb = (const float*)d_in[12];
    const float* d1fW = (const float*)d_in[13];
    const float* d1fU = (const float*)d_in[14];
    const float* d1fb = (const float*)d_in[15];
    const float* d1bW = (const float*)d_in[16];
    const float* d1bU = (const float*)d_in[17];
    const float* d1bb = (const float*)d_in[18];
    const float* d2fW = (const float*)d_in[19];
    const float* d2fU = (const float*)d_in[20];
    const float* d2fb = (const float*)d_in[21];
    const float* d2bW = (const float*)d_in[22];
    const float* d2bU = (const float*)d_in[23];
    const float* d2bb = (const float*)d_in[24];
    const float* Wd   = (const float*)d_in[25];
    const float* bd   = (const float*)d_in[26];

    float *p1, *p2, *p3;
    bf16 *xf, *h1f, *hd1f, *zhi, *zlo, *whi, *wlo;
    __half* wf;
    cudaGetSymbolAddress((void**)&p1,    g_xz1);
    cudaGetSymbolAddress((void**)&p2,    g_xz2);
    cudaGetSymbolAddress((void**)&p3,    g_xzd1);
    cudaGetSymbolAddress((void**)&xf,    g_xf);
    cudaGetSymbolAddress((void**)&h1f,   g_h1f);
    cudaGetSymbolAddress((void**)&hd1f,  g_hd1f);
    cudaGetSymbolAddress((void**)&zhi,   g_zhi);
    cudaGetSymbolAddress((void**)&zlo,   g_zlo);
    cudaGetSymbolAddress((void**)&whi,   g_whi);
    cudaGetSymbolAddress((void**)&wlo,   g_wlo);
    cudaGetSymbolAddress((void**)&wf,    g_wf);
    __half* xz1    = (__half*)p1;
    __half* xz2    = (__half*)p2;
    __half* xzd1   = (__half*)p3;
    __half* xf16   = (__half*)xf;
    __half* h1f16  = (__half*)h1f;
    __half* hd1f16 = (__half*)hd1f;

    // f16 weight offsets (halves): e1f, e1b, e2f, e2b, d2f, d2b, Wd
    const int F_e1f = 0,      F_e1b = 32768,  F_e2f = 65536, F_e2b = 131072;
    const int F_d2f = 196608, F_d2b = 262144, F_wd  = 327680;

    const int LS128 = 16 * 136 * 2 + 16 * 516 * 4;
    const int LS64  = 16 * 72 * 2 + 16 * 260 * 4;
    cudaFuncSetAttribute(lstm_tc<128, true, true>,
                         cudaFuncAttributeMaxDynamicSharedMemorySize, LS128);
    cudaFuncSetAttribute(lstm_tc<64, false, false>,
                         cudaFuncAttributeMaxDynamicSharedMemorySize, LS64);
    cudaFuncSetAttribute(lstm_tc<64, true, true>,
                         cudaFuncAttributeMaxDynamicSharedMemorySize, LS64);

    const int GS128 = 2 * (2 * 128 * 80 + 2 * 32 * 272);
    const int G1S   = 2 * (128 * 80 + 32 * 272);          // NT=128: 37888
    const int G1S64 = 2 * (128 * 80 + 32 * 144);          // NT=64 : 29696
    cudaFuncSetAttribute(hgemm2<128, 2, 4, __half>,
                         cudaFuncAttributeMaxDynamicSharedMemorySize, GS128);
    cudaFuncSetAttribute(hgemm1<128, 2, 4, __half>,
                         cudaFuncAttributeMaxDynamicSharedMemorySize, G1S);
    cudaFuncSetAttribute(hgemm1<64, 4, 2, float>,
                         cudaFuncAttributeMaxDynamicSharedMemorySize, G1S64);

    const int T = 256;

    cvt_x16<<<2048, 256>>>(x, xf16, 2097152);
    cvt_wf7<<<336, 256>>>(e1fW, e1bW, e2fW, e2bW, d2fW, d2bW, Wd, wf);
    cvt_w2<<<64, 256>>>(d1fW, d1bW, whi, wlo);

    // e1 (K=64, Nw=512, both dirs) — f16
    hgemm1<128, 2, 4, __half><<<dim3(4, 1024, 2), 256, G1S>>>(
        xf16, wf + F_e1f, wf + F_e1b, e1fb, e1bb, xz1, 64, 512, 1024, 512);
    lstm_tc<128, true, true><<<dim3(32, 2), 512, LS128>>>(
        xz1, (size_t)T * 1024, 1024, e1fU, e1bU, nullptr, nullptr, h1f16, 256, T);

    // e2 (K=256, Nw=256) — f16
    hgemm1<128, 2, 4, __half><<<dim3(2, 1024, 2), 256, G1S>>>(
        h1f16, wf + F_e2f, wf + F_e2b, e2fb, e2bb, xz2, 256, 256, 512, 256);
    lstm_tc<64, false, false><<<dim3(32, 2), 512, LS64>>>(
        xz2, (size_t)T * 512, 512, e2fU, e2bU, zhi, zlo, nullptr, 128, T);

    // d1 (M=512, K=128, Nw=256) — 3-term bf16 (z path kept accurate)
    hgemm2<128, 2, 4, __half><<<dim3(2, 4, 2), 256, GS128>>>(
        zhi, zlo, whi, wlo, whi + 32768, wlo + 32768,
        d1fb, d1bb, xzd1, 128, 256, 512, 256);
    lstm_tc<64, true, true><<<dim3(32, 2), 512, LS64>>>(
        xzd1, 512, 0, d1fU, d1bU, nullptr, nullptr, hd1f16, 128, T);

    // d2 (K=128, Nw=512) — f16
    hgemm1<128, 2, 4, __half><<<dim3(4, 1024, 2), 256, G1S>>>(
        hd1f16, wf + F_d2f, wf + F_d2b, d2fb, d2bb, xz1, 128, 512, 1024, 512);
    lstm_tc<128, true, true><<<dim3(32, 2), 512, LS128>>>(
        xz1, (size_t)T * 1024, 1024, d2fU, d2bU, nullptr, nullptr, h1f16, 256, T);

    // dense (K=256, Nw=64, single dir, fp32 out) — f16
    hgemm1<64, 4, 2, float><<<dim3(1, 1024, 1), 256, G1S64>>>(
        h1f16, wf + F_wd, wf + F_wd, bd, bd, (float*)d_out, 256, 64, 64, 0);
}